// round 4
// baseline (speedup 1.0000x reference)
#include <cuda_runtime.h>
#include <math.h>

// Problem dims
#define NXc 128
#define NYc 64
#define NMc 32
#define NDTc 32
#define NUc 32
#define NDc 32
#define NSTEPSc 1024
#define Bc 128
#define TPc 64

// Output offsets (floats) for the flattened 11-tuple
#define OFF_X      ((size_t)0)
#define OFF_Y      ((size_t)16777216)
#define OFF_U      ((size_t)25165824)
#define OFF_SXMIN  ((size_t)29360128)
#define OFF_SXMAX  ((size_t)46137344)
#define OFF_SUMIN  ((size_t)62914560)
#define OFF_SUMAX  ((size_t)67108864)
#define OFF_SDXX   ((size_t)71303168)
#define OFF_SDXU   ((size_t)88080384)
#define OFF_SDXD   ((size_t)104857600)
#define OFF_SPECT  ((size_t)121634816)

// ---------------- module-scope scratch ----------------
__device__ float g_WA[NXc * NXc];
__device__ float g_WC[NXc * NYc];
__device__ float g_WE[NDc * NXc];
__device__ float g_WB[NUc * NXc];
__device__ float g_bvec[NXc];
__device__ float g_x0[Bc * NXc];
__device__ float g_C[(size_t)NSTEPSc * Bc * NXc];
__device__ float g_acc[8];

__device__ __forceinline__ float sigmoid_f(float x) { return 1.0f / (1.0f + expf(-x)); }
__device__ __forceinline__ float relu_f(float x) { return fmaxf(x, 0.0f); }
__device__ __forceinline__ float gelu_tanh(float x) {
    float x3 = x * x * x;
    float t = tanhf(0.7978845608028654f * (x + 0.044715f * x3));
    return 0.5f * x * (1.0f + t);
}

// ---------------- kernel 0: zero accumulators --------------------------------
__global__ void k_zero() {
    if (threadIdx.x < 8) g_acc[threadIdx.x] = 0.0f;
}

// ---------------- kernel 1: spectral weights + Gram sums ---------------------
__global__ void __launch_bounds__(128) k_setup(
    const float* __restrict__ UA, const float* __restrict__ sigA, const float* __restrict__ VA,
    const float* __restrict__ UC, const float* __restrict__ sigC, const float* __restrict__ VC)
{
    __shared__ float sA[128], sC[64], rowUA[128], rowUC[64];
    __shared__ float colUA[128], colVA[128], colUC[128], colVC[64];
    __shared__ float red[4];
    int i = blockIdx.x, j = threadIdx.x;

    sA[j] = 0.1f + 0.8f * sigmoid_f(sigA[j]);
    rowUA[j] = UA[i * 128 + j];
    colUA[j] = UA[j * 128 + i];
    colVA[j] = VA[j * 128 + i];
    colUC[j] = UC[j * 128 + i];
    if (j < 64) {
        sC[j] = 0.9f + 0.1f * sigmoid_f(sigC[j]);
        rowUC[j] = UC[i * 128 + j];
        if (i < 64) colVC[j] = VC[j * 64 + i];
    }
    __syncthreads();

    float acc = 0.0f;
    #pragma unroll 8
    for (int k = 0; k < 128; k++) acc = fmaf(rowUA[k] * sA[k], VA[k * 128 + j], acc);
    g_WA[i * 128 + j] = acc;

    if (j < 64) {
        float a = 0.0f;
        #pragma unroll 8
        for (int k = 0; k < 64; k++) a = fmaf(rowUC[k] * sC[k], VC[k * 64 + j], a);
        g_WC[i * 64 + j] = a;
    }

    float gua = 0.0f, gva = 0.0f, guc = 0.0f;
    #pragma unroll 8
    for (int k = 0; k < 128; k++) {
        gua = fmaf(colUA[k], UA[k * 128 + j], gua);
        gva = fmaf(colVA[k], VA[k * 128 + j], gva);
        guc = fmaf(colUC[k], UC[k * 128 + j], guc);
    }
    float p6 = 0.0f, p7 = 0.0f;
    if (i < 64 && j < 64) {
        float g = 0.0f;
        #pragma unroll 8
        for (int k = 0; k < 64; k++) g = fmaf(colVC[k], VC[k * 64 + j], g);
        p6 = g * g;
        float v = VC[i * 64 + j];
        p7 = v * v;
    }
    float part[8];
    part[0] = gua * gua;
    part[1] = rowUA[j] * rowUA[j];
    part[2] = gva * gva;
    { float v = VA[i * 128 + j]; part[3] = v * v; }
    part[4] = guc * guc;
    { float v = UC[i * 128 + j]; part[5] = v * v; }
    part[6] = p6;
    part[7] = p7;

    for (int v = 0; v < 8; v++) {
        float x = part[v];
        #pragma unroll
        for (int o = 16; o; o >>= 1) x += __shfl_xor_sync(0xffffffffu, x, o);
        if ((j & 31) == 0) red[j >> 5] = x;
        __syncthreads();
        if (j == 0) atomicAdd(&g_acc[v], red[0] + red[1] + red[2] + red[3]);
        __syncthreads();
    }
}

// ---------------- kernel 2: W_E, W_B, bvec, SpectErr -------------------------
__global__ void __launch_bounds__(128) k_setup2(
    const float* __restrict__ x0c, const float* __restrict__ wE,
    const float* __restrict__ sE, const float* __restrict__ wB,
    float* __restrict__ out)
{
    __shared__ float xc[128];
    int j = threadIdx.x;
    xc[j] = x0c[j];
    __syncthreads();

    float b = 0.0f;
    #pragma unroll 8
    for (int k = 0; k < 128; k++) b = fmaf(xc[k], g_WA[k * 128 + j], b);
    g_bvec[j] = b;

    float mx = -1e30f;
    for (int i = 0; i < 32; i++) mx = fmaxf(mx, wE[i * 128 + j]);
    float s = 0.0f;
    for (int i = 0; i < 32; i++) s += expf(wE[i * 128 + j] - mx);
    float inv = 1.0f / s;
    for (int i = 0; i < 32; i++) {
        float sm = expf(wE[i * 128 + j] - mx) * inv;
        float sc = 1.0f - 0.95f * sigmoid_f(sE[i * 128 + j]);
        g_WE[i * 128 + j] = sc * sm;
    }
    for (int idx = j; idx < NUc * NXc; idx += 128) g_WB[idx] = relu_f(wB[idx]);

    float errA = (g_acc[0] - 2.0f * g_acc[1] + 128.0f) * (1.0f / 16384.0f)
               + (g_acc[2] - 2.0f * g_acc[3] + 128.0f) * (1.0f / 16384.0f);
    float errC = (g_acc[4] - 2.0f * g_acc[5] + 128.0f) * (1.0f / 16384.0f)
               + (g_acc[6] - 2.0f * g_acc[7] + 64.0f) * (1.0f / 4096.0f);
    float sp = errA + errC;
    for (int idx = j; idx < NSTEPSc; idx += 128) out[OFF_SPECT + idx] = sp;
}

// ---------------- kernel 3: RNN warmup (quad-split, 1 barrier/step) ----------
__global__ void __launch_bounds__(512) k_rnn(
    const float* __restrict__ Ym, const float* __restrict__ Wih,
    const float* __restrict__ Whh)
{
    __shared__ float h2[2][128];
    __shared__ float ym_sh[2][64];
    int tid = threadIdx.x;
    int b = blockIdx.x;
    int j = tid >> 2, h = tid & 3;

    float whh[32];
    #pragma unroll
    for (int kk = 0; kk < 32; kk++) whh[kk] = Whh[(h * 32 + kk) * 128 + j];
    float wih[16];
    #pragma unroll
    for (int kk = 0; kk < 16; kk++) wih[kk] = Wih[(h * 16 + kk) * 128 + j];

    if (tid < 128) h2[0][tid] = 0.0f;
    if (tid >= 448) ym_sh[0][tid - 448] = Ym[(size_t)b * 64 + (tid - 448)];
    __syncthreads();

    for (int t = 0; t < TPc; t++) {
        int cur = t & 1;
        float a0 = 0.0f, a1 = 0.0f;
        const float* yc = ym_sh[cur];
        #pragma unroll
        for (int kk = 0; kk < 16; kk += 2) {
            a0 = fmaf(yc[h * 16 + kk],     wih[kk],     a0);
            a1 = fmaf(yc[h * 16 + kk + 1], wih[kk + 1], a1);
        }
        const float* hc = h2[cur];
        #pragma unroll
        for (int kk = 0; kk < 32; kk += 2) {
            a0 = fmaf(hc[h * 32 + kk],     whh[kk],     a0);
            a1 = fmaf(hc[h * 32 + kk + 1], whh[kk + 1], a1);
        }
        float acc = a0 + a1;
        acc += __shfl_xor_sync(0xffffffffu, acc, 1);
        acc += __shfl_xor_sync(0xffffffffu, acc, 2);
        if (tid >= 448 && t + 1 < TPc)
            ym_sh[1 - cur][tid - 448] = Ym[((size_t)(t + 1) * Bc + b) * 64 + (tid - 448)];
        if (h == 0) h2[1 - cur][j] = gelu_tanh(acc);
        __syncthreads();
    }
    if (tid < 128) g_x0[b * 128 + tid] = h2[0][tid];
}

// ---------------- kernel 4: precompute (u, Bu, Ed, slacks) -------------------
// 512 threads, one block per t. Single barrier per sample b:
//   phase b: S1 computes u(b) [all threads, Whf in regs, 16-lane shfl reduce]
//            S0 builds g(b+1)  [threads 0..255]
//            S2 drains outputs for b-1 [threads 256..415, W_B/W_E from smem]
#define SM_PRE_FLOATS (4096*2 + 4096*3 + 2048 + 64 + 128*3)
__global__ void __launch_bounds__(512) k_pre(
    const float* __restrict__ M, const float* __restrict__ DTin,
    const float* __restrict__ Din, const float* __restrict__ UMIN,
    const float* __restrict__ UMAX, const float* __restrict__ Whf,
    const float* __restrict__ dxmn_g, const float* __restrict__ dxmx_g,
    float* __restrict__ out)
{
    extern __shared__ float sm[];
    float* wb_sh   = sm;            // 4096
    float* we_sh   = sm + 4096;     // 4096
    float* m_all   = sm + 8192;     // 4096
    float* dt_all  = sm + 12288;    // 4096
    float* d_all   = sm + 16384;    // 4096
    float* g2      = sm + 20480;    // 2 x 1024
    float* u_sh    = sm + 22528;    // 2 x 32
    float* bvec_sh = sm + 22592;    // 128
    float* dxmn_sh = sm + 22720;    // 128
    float* dxmx_sh = sm + 22848;    // 128

    int tid = threadIdx.x;
    int t = blockIdx.x;
    int o = tid >> 4, l = tid & 15;
    int lh = l >> 3, lj = l & 7;

    // Whf -> registers, 16-way split per output o
    float4 w[16];
    const float4* whf4 = (const float4*)Whf;
    #pragma unroll
    for (int i = 0; i < 16; i++)
        w[i] = whf4[(o * 32 + lh * 16 + i) * 8 + lj];

    size_t tb = (size_t)t * 4096;
    {
        const float4* M4  = (const float4*)(M + tb);
        const float4* DT4 = (const float4*)(DTin + tb);
        const float4* D4  = (const float4*)(Din + tb);
        float4* m4  = (float4*)m_all;
        float4* dt4 = (float4*)dt_all;
        float4* d4  = (float4*)d_all;
        #pragma unroll
        for (int idx = tid; idx < 1024; idx += 512) {
            m4[idx] = M4[idx];
            dt4[idx] = DT4[idx];
            d4[idx] = D4[idx];
        }
    }
    for (int idx = tid; idx < 4096; idx += 512) {
        wb_sh[idx] = g_WB[idx];
        we_sh[idx] = g_WE[idx];
    }
    if (tid < 128) {
        bvec_sh[tid] = g_bvec[tid];
        dxmn_sh[tid] = dxmn_g[tid];
        dxmx_sh[tid] = dxmx_g[tid];
    }
    // UMIN/UMAX prefetch ring (threads 384..415), depth 2
    int uo = tid - 384;
    float umn_pf[2] = {0.f, 0.f}, umx_pf[2] = {0.f, 0.f};
    if (uo >= 0 && uo < 32) {
        umn_pf[0] = UMIN[tb + uo];
        umx_pf[0] = UMAX[tb + uo];
        umn_pf[1] = UMIN[tb + 32 + uo];
        umx_pf[1] = UMAX[tb + 32 + uo];
    }
    __syncthreads();
    // build g for b=0
    if (tid < 256) {
        int idx = tid * 4;
        int gi = idx >> 5, gj4 = (idx & 31) >> 2;
        float4 dv = ((const float4*)dt_all)[gj4];
        float mi = m_all[gi];
        ((float4*)g2)[tid] = make_float4(mi * dv.x, mi * dv.y, mi * dv.z, mi * dv.w);
    }
    __syncthreads();

    for (int bp = 0; bp <= 128; bp++) {
        int cur = bp & 1;

        // ---- S1: bilinear u for sample bp (runs unconditionally; bp==128 writes an unused slot)
        {
            const float4* g4 = (const float4*)(g2 + cur * 1024);
            float a0 = 0.0f, a1 = 0.0f;
            #pragma unroll
            for (int i = 0; i < 16; i += 2) {
                float4 gv0 = g4[(lh * 16 + i) * 8 + lj];
                float4 gv1 = g4[(lh * 16 + i + 1) * 8 + lj];
                a0 = fmaf(w[i].x, gv0.x, a0);
                a0 = fmaf(w[i].y, gv0.y, a0);
                a0 = fmaf(w[i].z, gv0.z, a0);
                a0 = fmaf(w[i].w, gv0.w, a0);
                a1 = fmaf(w[i + 1].x, gv1.x, a1);
                a1 = fmaf(w[i + 1].y, gv1.y, a1);
                a1 = fmaf(w[i + 1].z, gv1.z, a1);
                a1 = fmaf(w[i + 1].w, gv1.w, a1);
            }
            float acc = a0 + a1;
            acc += __shfl_xor_sync(0xffffffffu, acc, 1);
            acc += __shfl_xor_sync(0xffffffffu, acc, 2);
            acc += __shfl_xor_sync(0xffffffffu, acc, 4);
            acc += __shfl_xor_sync(0xffffffffu, acc, 8);
            if (l == 0) u_sh[cur * 32 + o] = acc;
        }

        // ---- S0: build g for bp+1
        if (tid < 256 && bp + 1 < 128) {
            int idx = tid * 4;
            int gi = idx >> 5, gj4 = (idx & 31) >> 2;
            float4 dv = ((const float4*)(dt_all + (bp + 1) * 32))[gj4];
            float mi = m_all[(bp + 1) * 32 + gi];
            ((float4*)(g2 + (1 - cur) * 1024))[tid] =
                make_float4(mi * dv.x, mi * dv.y, mi * dv.z, mi * dv.w);
        }

        // ---- S2: drain outputs for sample b2 = bp-1
        if (bp >= 1) {
            int b2 = bp - 1;
            int pv = b2 & 1;
            if (tid >= 256 && tid < 384) {
                int c = tid - 256;
                float bu = 0.0f, ed = 0.0f;
                #pragma unroll
                for (int oo = 0; oo < 32; oo++) {
                    bu = fmaf(u_sh[pv * 32 + oo], wb_sh[oo * 128 + c], bu);
                    ed = fmaf(d_all[b2 * 32 + oo], we_sh[oo * 128 + c], ed);
                }
                size_t base128 = ((size_t)t * Bc + b2) * 128;
                float dn = dxmn_sh[c], dx = dxmx_sh[c];
                out[OFF_SDXU + base128 + c] = relu_f(dn - bu) + relu_f(bu - dx);
                out[OFF_SDXD + base128 + c] = relu_f(dn - ed) + relu_f(ed - dx);
                g_C[base128 + c] = bu + ed + bvec_sh[c];
            } else if (uo >= 0 && uo < 32) {
                float uu = u_sh[pv * 32 + uo];
                size_t base32 = tb + (size_t)b2 * 32;
                int s = b2 & 1;
                out[OFF_U + base32 + uo]     = uu;
                out[OFF_SUMIN + base32 + uo] = relu_f(umn_pf[s] - uu);
                out[OFF_SUMAX + base32 + uo] = relu_f(uu - umx_pf[s]);
                if (b2 + 2 < 128) {
                    umn_pf[s] = UMIN[base32 + 64 + uo];
                    umx_pf[s] = UMAX[base32 + 64 + uo];
                }
            }
        }
        __syncthreads();
    }
}

// ---------------- kernel 5: sequential rollout -------------------------------
// 512 threads, quad k-split (shfl reduce), triple-buffered x, 1 barrier/step.
// C staged via 8-slot smem ring (LDG->STS, 2-phase cover); XMIN/XMAX in
// depth-4 register rings on threads 0..127 which also do the coalesced stores.
__global__ void __launch_bounds__(512) k_seq(
    const float* __restrict__ XMIN, const float* __restrict__ XMAX,
    const float* __restrict__ Cg, float* __restrict__ out)
{
    __shared__ float x3[3][128];
    __shared__ float c_sh[8][128];
    int tid = threadIdx.x;
    int b = blockIdx.x;
    int j = tid >> 2, h = tid & 3;

    float wa[32];
    #pragma unroll
    for (int kk = 0; kk < 32; kk++) wa[kk] = g_WA[(h * 32 + kk) * 128 + j];

    float mnr[4], mxr[4], creg[2];
    if (tid < 128) {
        #pragma unroll
        for (int s = 0; s < 4; s++) {
            size_t idx = ((size_t)s * Bc + b) * 128 + tid;
            mnr[s] = XMIN[idx];
            mxr[s] = XMAX[idx];
            c_sh[s][tid] = Cg[idx];
        }
        creg[0] = Cg[((size_t)4 * Bc + b) * 128 + tid];
        creg[1] = Cg[((size_t)5 * Bc + b) * 128 + tid];
        x3[0][tid] = g_x0[b * 128 + tid];
    }
    __syncthreads();

    int cur = 0;
    for (int p = 0; p <= NSTEPSc; p++) {
        int nxt = (cur == 2) ? 0 : cur + 1;
        int old = (cur == 0) ? 2 : cur - 1;

        // compute x_{p+1}
        float a0 = 0.0f, a1 = 0.0f;
        const float4* x4 = ((const float4*)x3[cur]) + h * 8;
        #pragma unroll
        for (int kk = 0; kk < 4; kk++) {
            float4 v0 = x4[kk * 2];
            float4 v1 = x4[kk * 2 + 1];
            a0 = fmaf(v0.x, wa[kk * 8 + 0], a0);
            a0 = fmaf(v0.y, wa[kk * 8 + 1], a0);
            a0 = fmaf(v0.z, wa[kk * 8 + 2], a0);
            a0 = fmaf(v0.w, wa[kk * 8 + 3], a0);
            a1 = fmaf(v1.x, wa[kk * 8 + 4], a1);
            a1 = fmaf(v1.y, wa[kk * 8 + 5], a1);
            a1 = fmaf(v1.z, wa[kk * 8 + 6], a1);
            a1 = fmaf(v1.w, wa[kk * 8 + 7], a1);
        }
        float acc = a0 + a1;
        acc += __shfl_xor_sync(0xffffffffu, acc, 1);
        acc += __shfl_xor_sync(0xffffffffu, acc, 2);
        if (h == 0 && p < NSTEPSc)
            x3[nxt][j] = acc + c_sh[p & 7][j];

        if (tid < 128) {
            // refill C ring: slot (p+4), value loaded 2 phases ago
            if (p + 4 < NSTEPSc) c_sh[(p + 4) & 7][tid] = creg[p & 1];
            if (p + 6 < NSTEPSc) creg[p & 1] = Cg[((size_t)(p + 6) * Bc + b) * 128 + tid];

            // outputs for step t = p-1 (reads x_{p} and x_{p-1} from smem)
            if (p >= 1) {
                int tt = p - 1;
                int s = tt & 3;
                float xn = x3[cur][tid];
                float xo = x3[old][tid];
                size_t bi = ((size_t)tt * Bc + b) * 128 + tid;
                out[OFF_X + bi]     = xn;
                out[OFF_SXMIN + bi] = relu_f(mnr[s] - xn);
                out[OFF_SXMAX + bi] = relu_f(xn - mxr[s]);
                out[OFF_SDXX + bi]  = xn - xo;
                if (tt + 4 < NSTEPSc) {
                    size_t i4 = ((size_t)(tt + 4) * Bc + b) * 128 + tid;
                    mnr[s] = XMIN[i4];
                    mxr[s] = XMAX[i4];
                }
            }
        }
        __syncthreads();
        cur = nxt;
    }
}

// ---------------- kernel 6: Y = X @ W_C (fully parallel) ---------------------
__global__ void __launch_bounds__(256) k_post(float* __restrict__ out)
{
    __shared__ float x2[256];
    __shared__ float p2[128];
    int tid = threadIdx.x;
    size_t row0 = (size_t)blockIdx.x * 2;
    int r = tid >> 7;
    int q = (tid >> 6) & 1, j2 = tid & 63;

    float wc[64];
    #pragma unroll
    for (int kk = 0; kk < 64; kk++) wc[kk] = g_WC[(q * 64 + kk) * 64 + j2];

    x2[tid] = out[OFF_X + row0 * 128 + tid];
    __syncthreads();

    float part = 0.0f;
    const float* xr = x2 + r * 128 + q * 64;
    #pragma unroll
    for (int kk = 0; kk < 64; kk++) part = fmaf(xr[kk], wc[kk], part);

    if (q == 1) p2[r * 64 + j2] = part;
    __syncthreads();
    if (q == 0)
        out[OFF_Y + row0 * 64 + (size_t)r * 64 + j2] = part + p2[r * 64 + j2];
}

// ---------------- launch ------------------------------------------------------
extern "C" void kernel_launch(void* const* d_in, const int* in_sizes, int n_in,
                              void* d_out, int out_size)
{
    const float* Ym   = (const float*)d_in[0];
    const float* M    = (const float*)d_in[1];
    const float* DTin = (const float*)d_in[2];
    const float* Din  = (const float*)d_in[3];
    const float* XMIN = (const float*)d_in[4];
    const float* XMAX = (const float*)d_in[5];
    const float* UMIN = (const float*)d_in[6];
    const float* UMAX = (const float*)d_in[7];
    const float* x0c  = (const float*)d_in[8];
    const float* UA   = (const float*)d_in[9];
    const float* sigA = (const float*)d_in[10];
    const float* VA   = (const float*)d_in[11];
    const float* UC   = (const float*)d_in[12];
    const float* sigC = (const float*)d_in[13];
    const float* VC   = (const float*)d_in[14];
    const float* wE   = (const float*)d_in[15];
    const float* sE   = (const float*)d_in[16];
    const float* wB   = (const float*)d_in[17];
    const float* Whf  = (const float*)d_in[18];
    const float* Wih  = (const float*)d_in[19];
    const float* Whh  = (const float*)d_in[20];
    const float* dxmn = (const float*)d_in[21];
    const float* dxmx = (const float*)d_in[22];
    float* out = (float*)d_out;

    static const size_t smem_pre = SM_PRE_FLOATS * sizeof(float);
    cudaFuncSetAttribute(k_pre, cudaFuncAttributeMaxDynamicSharedMemorySize,
                         (int)smem_pre);

    float* Cg = nullptr;
    cudaGetSymbolAddress((void**)&Cg, g_C);

    k_zero<<<1, 32>>>();
    k_setup<<<128, 128>>>(UA, sigA, VA, UC, sigC, VC);
    k_setup2<<<1, 128>>>(x0c, wE, sE, wB, out);
    k_rnn<<<Bc, 512>>>(Ym, Wih, Whh);
    k_pre<<<NSTEPSc, 512, smem_pre>>>(M, DTin, Din, UMIN, UMAX, Whf, dxmn, dxmx, out);
    k_seq<<<Bc, 512>>>(XMIN, XMAX, Cg, out);
    k_post<<<(NSTEPSc * Bc) / 2, 256>>>(out);
}

// round 5
// speedup vs baseline: 1.7178x; 1.7178x over previous
#include <cuda_runtime.h>
#include <math.h>

// Problem dims
#define NXc 128
#define NYc 64
#define NMc 32
#define NDTc 32
#define NUc 32
#define NDc 32
#define NSTEPSc 1024
#define Bc 128
#define TPc 64

// Output offsets (floats) for the flattened 11-tuple
#define OFF_X      ((size_t)0)
#define OFF_Y      ((size_t)16777216)
#define OFF_U      ((size_t)25165824)
#define OFF_SXMIN  ((size_t)29360128)
#define OFF_SXMAX  ((size_t)46137344)
#define OFF_SUMIN  ((size_t)62914560)
#define OFF_SUMAX  ((size_t)67108864)
#define OFF_SDXX   ((size_t)71303168)
#define OFF_SDXU   ((size_t)88080384)
#define OFF_SDXD   ((size_t)104857600)
#define OFF_SPECT  ((size_t)121634816)

// ---------------- module-scope scratch ----------------
__device__ float g_WA[NXc * NXc];
__device__ float g_WC[NXc * NYc];
__device__ float g_WE[NDc * NXc];
__device__ float g_WB[NUc * NXc];
__device__ float g_bvec[NXc];
__device__ float g_x0[Bc * NXc];
__device__ float g_C[(size_t)NSTEPSc * Bc * NXc];
__device__ float g_acc[8];

__device__ __forceinline__ float sigmoid_f(float x) { return 1.0f / (1.0f + expf(-x)); }
__device__ __forceinline__ float relu_f(float x) { return fmaxf(x, 0.0f); }
__device__ __forceinline__ float gelu_tanh(float x) {
    float x3 = x * x * x;
    float t = tanhf(0.7978845608028654f * (x + 0.044715f * x3));
    return 0.5f * x * (1.0f + t);
}

// ---------------- kernel 0: zero accumulators --------------------------------
__global__ void k_zero() {
    if (threadIdx.x < 8) g_acc[threadIdx.x] = 0.0f;
}

// ---------------- kernel 1: spectral weights + Gram sums ---------------------
__global__ void __launch_bounds__(128) k_setup(
    const float* __restrict__ UA, const float* __restrict__ sigA, const float* __restrict__ VA,
    const float* __restrict__ UC, const float* __restrict__ sigC, const float* __restrict__ VC)
{
    __shared__ float sA[128], sC[64], rowUA[128], rowUC[64];
    __shared__ float colUA[128], colVA[128], colUC[128], colVC[64];
    __shared__ float red[4];
    int i = blockIdx.x, j = threadIdx.x;

    sA[j] = 0.1f + 0.8f * sigmoid_f(sigA[j]);
    rowUA[j] = UA[i * 128 + j];
    colUA[j] = UA[j * 128 + i];
    colVA[j] = VA[j * 128 + i];
    colUC[j] = UC[j * 128 + i];
    if (j < 64) {
        sC[j] = 0.9f + 0.1f * sigmoid_f(sigC[j]);
        rowUC[j] = UC[i * 128 + j];
        if (i < 64) colVC[j] = VC[j * 64 + i];
    }
    __syncthreads();

    float acc = 0.0f;
    #pragma unroll 8
    for (int k = 0; k < 128; k++) acc = fmaf(rowUA[k] * sA[k], VA[k * 128 + j], acc);
    g_WA[i * 128 + j] = acc;

    if (j < 64) {
        float a = 0.0f;
        #pragma unroll 8
        for (int k = 0; k < 64; k++) a = fmaf(rowUC[k] * sC[k], VC[k * 64 + j], a);
        g_WC[i * 64 + j] = a;
    }

    float gua = 0.0f, gva = 0.0f, guc = 0.0f;
    #pragma unroll 8
    for (int k = 0; k < 128; k++) {
        gua = fmaf(colUA[k], UA[k * 128 + j], gua);
        gva = fmaf(colVA[k], VA[k * 128 + j], gva);
        guc = fmaf(colUC[k], UC[k * 128 + j], guc);
    }
    float p6 = 0.0f, p7 = 0.0f;
    if (i < 64 && j < 64) {
        float g = 0.0f;
        #pragma unroll 8
        for (int k = 0; k < 64; k++) g = fmaf(colVC[k], VC[k * 64 + j], g);
        p6 = g * g;
        float v = VC[i * 64 + j];
        p7 = v * v;
    }
    float part[8];
    part[0] = gua * gua;
    part[1] = rowUA[j] * rowUA[j];
    part[2] = gva * gva;
    { float v = VA[i * 128 + j]; part[3] = v * v; }
    part[4] = guc * guc;
    { float v = UC[i * 128 + j]; part[5] = v * v; }
    part[6] = p6;
    part[7] = p7;

    for (int v = 0; v < 8; v++) {
        float x = part[v];
        #pragma unroll
        for (int o = 16; o; o >>= 1) x += __shfl_xor_sync(0xffffffffu, x, o);
        if ((j & 31) == 0) red[j >> 5] = x;
        __syncthreads();
        if (j == 0) atomicAdd(&g_acc[v], red[0] + red[1] + red[2] + red[3]);
        __syncthreads();
    }
}

// ---------------- kernel 2: W_E, W_B, bvec, SpectErr -------------------------
__global__ void __launch_bounds__(128) k_setup2(
    const float* __restrict__ x0c, const float* __restrict__ wE,
    const float* __restrict__ sE, const float* __restrict__ wB,
    float* __restrict__ out)
{
    __shared__ float xc[128];
    int j = threadIdx.x;
    xc[j] = x0c[j];
    __syncthreads();

    float b = 0.0f;
    #pragma unroll 8
    for (int k = 0; k < 128; k++) b = fmaf(xc[k], g_WA[k * 128 + j], b);
    g_bvec[j] = b;

    float mx = -1e30f;
    for (int i = 0; i < 32; i++) mx = fmaxf(mx, wE[i * 128 + j]);
    float s = 0.0f;
    for (int i = 0; i < 32; i++) s += expf(wE[i * 128 + j] - mx);
    float inv = 1.0f / s;
    for (int i = 0; i < 32; i++) {
        float sm = expf(wE[i * 128 + j] - mx) * inv;
        float sc = 1.0f - 0.95f * sigmoid_f(sE[i * 128 + j]);
        g_WE[i * 128 + j] = sc * sm;
    }
    for (int idx = j; idx < NUc * NXc; idx += 128) g_WB[idx] = relu_f(wB[idx]);

    float errA = (g_acc[0] - 2.0f * g_acc[1] + 128.0f) * (1.0f / 16384.0f)
               + (g_acc[2] - 2.0f * g_acc[3] + 128.0f) * (1.0f / 16384.0f);
    float errC = (g_acc[4] - 2.0f * g_acc[5] + 128.0f) * (1.0f / 16384.0f)
               + (g_acc[6] - 2.0f * g_acc[7] + 64.0f) * (1.0f / 4096.0f);
    float sp = errA + errC;
    for (int idx = j; idx < NSTEPSc; idx += 128) out[OFF_SPECT + idx] = sp;
}

// ---------------- kernel 3: RNN warmup (R3 proven version) -------------------
__global__ void __launch_bounds__(512) k_rnn(
    const float* __restrict__ Ym, const float* __restrict__ Wih,
    const float* __restrict__ Whh)
{
    __shared__ float h_sh[128];
    __shared__ float ym_sh[2][64];
    __shared__ float p_sh[3 * 128];
    int tid = threadIdx.x;
    int b = blockIdx.x;
    int j = tid & 127, h = tid >> 7;

    float whh_r[32];
    #pragma unroll
    for (int kk = 0; kk < 32; kk++) whh_r[kk] = Whh[(h * 32 + kk) * 128 + j];
    float wih_r[16];
    #pragma unroll
    for (int kk = 0; kk < 16; kk++) wih_r[kk] = Wih[(h * 16 + kk) * 128 + j];

    if (tid < 128) h_sh[tid] = 0.0f;
    if (tid >= 448) ym_sh[0][tid - 448] = Ym[(size_t)b * 64 + (tid - 448)];
    __syncthreads();

    for (int t = 0; t < TPc; t++) {
        const float* yc = ym_sh[t & 1];
        float acc = 0.0f;
        #pragma unroll
        for (int kk = 0; kk < 16; kk++)
            acc = fmaf(yc[h * 16 + kk], wih_r[kk], acc);
        #pragma unroll
        for (int kk = 0; kk < 32; kk++)
            acc = fmaf(h_sh[h * 32 + kk], whh_r[kk], acc);

        if (tid >= 448 && t + 1 < TPc)
            ym_sh[(t + 1) & 1][tid - 448] = Ym[((size_t)(t + 1) * Bc + b) * 64 + (tid - 448)];

        if (h) p_sh[(h - 1) * 128 + j] = acc;
        __syncthreads();
        if (h == 0)
            h_sh[j] = gelu_tanh(acc + p_sh[j] + p_sh[128 + j] + p_sh[256 + j]);
        __syncthreads();
    }
    if (tid < 128) g_x0[b * 128 + tid] = h_sh[tid];
}

// ---------------- kernel 4: precompute (u, Bu, Ed, slacks) -------------------
// One block per t, 256 threads, ONE barrier per sample via double-buffered g/u:
//  iteration bp: S1 computes u(bp) into u[bp&1] (reads g[bp&1]);
//                S0 builds g(bp+1) into g[1-(bp&1)];
//                S2 drains outputs for bp-1 (reads u[1-(bp&1)]); sync.
#define SM_PRE_FLOATS (4096*3 + 2048 + 64 + 128*3)
__global__ void __launch_bounds__(256) k_pre(
    const float* __restrict__ M, const float* __restrict__ DTin,
    const float* __restrict__ Din, const float* __restrict__ UMIN,
    const float* __restrict__ UMAX, const float* __restrict__ Whf,
    const float* __restrict__ dxmn_g, const float* __restrict__ dxmx_g,
    float* __restrict__ out)
{
    extern __shared__ float sm[];
    float* m_all   = sm;             // 4096
    float* dt_all  = sm + 4096;      // 4096
    float* d_all   = sm + 8192;      // 4096
    float* g2      = sm + 12288;     // 2 x 1024
    float* u_sh    = sm + 14336;     // 2 x 32
    float* bvec_sh = sm + 14400;     // 128
    float* dxmn_sh = sm + 14528;     // 128
    float* dxmx_sh = sm + 14656;     // 128

    int tid = threadIdx.x;
    int t = blockIdx.x;
    int o = tid >> 3, l = tid & 7;

    // W_hf -> registers (thread (o,l) holds W_hf[o][*][l*4..l*4+3])
    float4 w[32];
    const float4* whf4 = (const float4*)Whf;
    #pragma unroll
    for (int i = 0; i < 32; i++) w[i] = whf4[(o * 32 + i) * 8 + l];

    // W_B / W_E columns -> registers (threads 0..127)
    float wb_r[32], we_r[32];
    if (tid < 128) {
        #pragma unroll
        for (int oo = 0; oo < 32; oo++) {
            wb_r[oo] = g_WB[oo * 128 + tid];
            we_r[oo] = g_WE[oo * 128 + tid];
        }
    }

    size_t tb = (size_t)t * 4096;
    {
        const float4* M4  = (const float4*)(M + tb);
        const float4* DT4 = (const float4*)(DTin + tb);
        const float4* D4  = (const float4*)(Din + tb);
        float4* m4  = (float4*)m_all;
        float4* dt4 = (float4*)dt_all;
        float4* d4  = (float4*)d_all;
        #pragma unroll
        for (int idx = tid; idx < 1024; idx += 256) {
            m4[idx] = M4[idx];
            dt4[idx] = DT4[idx];
            d4[idx] = D4[idx];
        }
    }
    if (tid < 128) {
        bvec_sh[tid] = g_bvec[tid];
        dxmn_sh[tid] = dxmn_g[tid];
        dxmx_sh[tid] = dxmx_g[tid];
    }
    // UMIN/UMAX register ring (threads 128..159), depth 2
    int uo = tid - 128;
    float umnr[2] = {0.f, 0.f}, umxr[2] = {0.f, 0.f};
    if (uo >= 0 && uo < 32) {
        umnr[0] = UMIN[tb + uo];
        umxr[0] = UMAX[tb + uo];
        umnr[1] = UMIN[tb + 32 + uo];
        umxr[1] = UMAX[tb + 32 + uo];
    }
    __syncthreads();
    // build g for b=0
    {
        int idx = tid * 4;
        int gi = idx >> 5, gj4 = (idx & 31) >> 2;
        float4 dv = ((const float4*)dt_all)[gj4];
        float mi = m_all[gi];
        ((float4*)g2)[tid] = make_float4(mi * dv.x, mi * dv.y, mi * dv.z, mi * dv.w);
    }
    __syncthreads();

    for (int bp = 0; bp <= 128; bp++) {
        int cur = bp & 1;

        // ---- S1: bilinear u(bp)
        if (bp < 128) {
            const float4* g4 = (const float4*)(g2 + cur * 1024);
            float a0 = 0.0f, a1 = 0.0f;
            #pragma unroll
            for (int i = 0; i < 32; i += 2) {
                float4 gv0 = g4[i * 8 + l];
                float4 gv1 = g4[(i + 1) * 8 + l];
                a0 = fmaf(w[i].x, gv0.x, a0);
                a0 = fmaf(w[i].y, gv0.y, a0);
                a0 = fmaf(w[i].z, gv0.z, a0);
                a0 = fmaf(w[i].w, gv0.w, a0);
                a1 = fmaf(w[i + 1].x, gv1.x, a1);
                a1 = fmaf(w[i + 1].y, gv1.y, a1);
                a1 = fmaf(w[i + 1].z, gv1.z, a1);
                a1 = fmaf(w[i + 1].w, gv1.w, a1);
            }
            float acc = a0 + a1;
            acc += __shfl_xor_sync(0xffffffffu, acc, 1);
            acc += __shfl_xor_sync(0xffffffffu, acc, 2);
            acc += __shfl_xor_sync(0xffffffffu, acc, 4);
            if (l == 0) u_sh[cur * 32 + o] = acc;
        }

        // ---- S0: build g(bp+1) into the other buffer
        if (bp + 1 < 128) {
            int idx = tid * 4;
            int gi = idx >> 5, gj4 = (idx & 31) >> 2;
            float4 dv = ((const float4*)(dt_all + (bp + 1) * 32))[gj4];
            float mi = m_all[(bp + 1) * 32 + gi];
            ((float4*)(g2 + (1 - cur) * 1024))[tid] =
                make_float4(mi * dv.x, mi * dv.y, mi * dv.z, mi * dv.w);
        }

        // ---- S2: drain outputs for b2 = bp-1
        if (bp >= 1) {
            int b2 = bp - 1;
            int pv = b2 & 1;
            if (tid < 128) {
                float bu = 0.0f, ed = 0.0f;
                #pragma unroll
                for (int oo = 0; oo < 32; oo++) {
                    bu = fmaf(u_sh[pv * 32 + oo], wb_r[oo], bu);
                    ed = fmaf(d_all[b2 * 32 + oo], we_r[oo], ed);
                }
                size_t base128 = ((size_t)t * Bc + b2) * 128;
                float dn = dxmn_sh[tid], dx = dxmx_sh[tid];
                out[OFF_SDXU + base128 + tid] = relu_f(dn - bu) + relu_f(bu - dx);
                out[OFF_SDXD + base128 + tid] = relu_f(dn - ed) + relu_f(ed - dx);
                g_C[base128 + tid] = bu + ed + bvec_sh[tid];
            } else if (uo < 32) {
                float uu = u_sh[pv * 32 + uo];
                size_t base32 = tb + (size_t)b2 * 32;
                out[OFF_U + base32 + uo]     = uu;
                out[OFF_SUMIN + base32 + uo] = relu_f(umnr[pv] - uu);
                out[OFF_SUMAX + base32 + uo] = relu_f(uu - umxr[pv]);
                if (b2 + 2 < 128) {
                    umnr[pv] = UMIN[base32 + 64 + uo];
                    umxr[pv] = UMAX[base32 + 64 + uo];
                }
            }
        }
        __syncthreads();
    }
}

// ---------------- kernel 5: sequential rollout (R3 + depth-3 prefetch) -------
__global__ void __launch_bounds__(512) k_seq(
    const float* __restrict__ XMIN, const float* __restrict__ XMAX,
    const float* __restrict__ Cg, float* __restrict__ out)
{
    __shared__ float x_sh[128];
    __shared__ float p_sh[3 * 128];
    int tid = threadIdx.x;
    int b = blockIdx.x;
    int j = tid & 127, h = tid >> 7;

    float wa[32];
    #pragma unroll
    for (int kk = 0; kk < 32; kk++) wa[kk] = g_WA[(h * 32 + kk) * 128 + j];

    if (tid < 128) x_sh[tid] = g_x0[b * 128 + tid];

    float c0 = 0, c1 = 0, c2 = 0;
    float mn0 = 0, mn1 = 0, mn2 = 0, mx0 = 0, mx1 = 0, mx2 = 0;
    if (h == 0) {
        size_t i0 = ((size_t)0 * Bc + b) * 128 + j;
        size_t i1 = ((size_t)1 * Bc + b) * 128 + j;
        size_t i2 = ((size_t)2 * Bc + b) * 128 + j;
        c0 = Cg[i0]; mn0 = XMIN[i0]; mx0 = XMAX[i0];
        c1 = Cg[i1]; mn1 = XMIN[i1]; mx1 = XMAX[i1];
        c2 = Cg[i2]; mn2 = XMIN[i2]; mx2 = XMAX[i2];
    }
    __syncthreads();

    for (int t = 0; t < NSTEPSc; t++) {
        float acc = 0.0f;
        const float4* x4 = ((const float4*)x_sh) + h * 8;
        #pragma unroll
        for (int kk = 0; kk < 8; kk++) {
            float4 xv = x4[kk];
            acc = fmaf(xv.x, wa[kk * 4 + 0], acc);
            acc = fmaf(xv.y, wa[kk * 4 + 1], acc);
            acc = fmaf(xv.z, wa[kk * 4 + 2], acc);
            acc = fmaf(xv.w, wa[kk * 4 + 3], acc);
        }
        // prefetch t+3
        float cn = 0, mnn = 0, mxn = 0;
        if (h == 0 && t + 3 < NSTEPSc) {
            size_t i3 = ((size_t)(t + 3) * Bc + b) * 128 + j;
            cn = Cg[i3]; mnn = XMIN[i3]; mxn = XMAX[i3];
        }
        if (h) p_sh[(h - 1) * 128 + j] = acc;
        __syncthreads();

        if (h == 0) {
            float xold = x_sh[j];
            float xn = acc + p_sh[j] + p_sh[128 + j] + p_sh[256 + j] + c0;
            size_t bi = ((size_t)t * Bc + b) * 128 + j;
            out[OFF_X + bi]     = xn;
            out[OFF_SXMIN + bi] = relu_f(mn0 - xn);
            out[OFF_SXMAX + bi] = relu_f(xn - mx0);
            out[OFF_SDXX + bi]  = xn - xold;
            x_sh[j] = xn;
            c0 = c1; mn0 = mn1; mx0 = mx1;
            c1 = c2; mn1 = mn2; mx1 = mx2;
            c2 = cn; mn2 = mnn; mx2 = mxn;
        }
        __syncthreads();
    }
}

// ---------------- kernel 6: Y = X @ W_C (64 rows/block, weights amortized) ---
__global__ void __launch_bounds__(256) k_post(float* __restrict__ out)
{
    __shared__ float xs[64 * 128];   // 32 KB
    int tid = threadIdx.x;
    size_t row0 = (size_t)blockIdx.x * 64;
    int r0 = tid >> 6, j2 = tid & 63;

    float wc[128];
    #pragma unroll
    for (int kk = 0; kk < 128; kk++) wc[kk] = g_WC[kk * 64 + j2];

    const float4* src = (const float4*)(out + OFF_X + row0 * 128);
    float4* dst4 = (float4*)xs;
    #pragma unroll
    for (int i = 0; i < 8; i++) dst4[tid + i * 256] = src[tid + i * 256];
    __syncthreads();

    #pragma unroll 4
    for (int it = 0; it < 16; it++) {
        int row = it * 4 + r0;
        const float* xr = xs + row * 128;
        float a0 = 0.0f, a1 = 0.0f;
        #pragma unroll
        for (int kk = 0; kk < 64; kk++) {
            a0 = fmaf(xr[kk],      wc[kk],      a0);
            a1 = fmaf(xr[64 + kk], wc[64 + kk], a1);
        }
        out[OFF_Y + (row0 + row) * 64 + j2] = a0 + a1;
    }
}

// ---------------- launch ------------------------------------------------------
extern "C" void kernel_launch(void* const* d_in, const int* in_sizes, int n_in,
                              void* d_out, int out_size)
{
    const float* Ym   = (const float*)d_in[0];
    const float* M    = (const float*)d_in[1];
    const float* DTin = (const float*)d_in[2];
    const float* Din  = (const float*)d_in[3];
    const float* XMIN = (const float*)d_in[4];
    const float* XMAX = (const float*)d_in[5];
    const float* UMIN = (const float*)d_in[6];
    const float* UMAX = (const float*)d_in[7];
    const float* x0c  = (const float*)d_in[8];
    const float* UA   = (const float*)d_in[9];
    const float* sigA = (const float*)d_in[10];
    const float* VA   = (const float*)d_in[11];
    const float* UC   = (const float*)d_in[12];
    const float* sigC = (const float*)d_in[13];
    const float* VC   = (const float*)d_in[14];
    const float* wE   = (const float*)d_in[15];
    const float* sE   = (const float*)d_in[16];
    const float* wB   = (const float*)d_in[17];
    const float* Whf  = (const float*)d_in[18];
    const float* Wih  = (const float*)d_in[19];
    const float* Whh  = (const float*)d_in[20];
    const float* dxmn = (const float*)d_in[21];
    const float* dxmx = (const float*)d_in[22];
    float* out = (float*)d_out;

    static const size_t smem_pre = SM_PRE_FLOATS * sizeof(float);
    cudaFuncSetAttribute(k_pre, cudaFuncAttributeMaxDynamicSharedMemorySize,
                         (int)smem_pre);

    float* Cg = nullptr;
    cudaGetSymbolAddress((void**)&Cg, g_C);

    k_zero<<<1, 32>>>();
    k_setup<<<128, 128>>>(UA, sigA, VA, UC, sigC, VC);
    k_setup2<<<1, 128>>>(x0c, wE, sE, wB, out);
    k_rnn<<<Bc, 512>>>(Ym, Wih, Whh);
    k_pre<<<NSTEPSc, 256, smem_pre>>>(M, DTin, Din, UMIN, UMAX, Whf, dxmn, dxmx, out);
    k_seq<<<Bc, 512>>>(XMIN, XMAX, Cg, out);
    k_post<<<(NSTEPSc * Bc) / 64, 256>>>(out);
}

// round 6
// speedup vs baseline: 1.7254x; 1.0044x over previous
#include <cuda_runtime.h>
#include <math.h>

// Problem dims
#define NXc 128
#define NYc 64
#define NMc 32
#define NDTc 32
#define NUc 32
#define NDc 32
#define NSTEPSc 1024
#define Bc 128
#define TPc 64

// Output offsets (floats) for the flattened 11-tuple
#define OFF_X      ((size_t)0)
#define OFF_Y      ((size_t)16777216)
#define OFF_U      ((size_t)25165824)
#define OFF_SXMIN  ((size_t)29360128)
#define OFF_SXMAX  ((size_t)46137344)
#define OFF_SUMIN  ((size_t)62914560)
#define OFF_SUMAX  ((size_t)67108864)
#define OFF_SDXX   ((size_t)71303168)
#define OFF_SDXU   ((size_t)88080384)
#define OFF_SDXD   ((size_t)104857600)
#define OFF_SPECT  ((size_t)121634816)

// ---------------- module-scope scratch ----------------
__device__ float g_WA[NXc * NXc];
__device__ float g_WC[NXc * NYc];
__device__ float g_WE[NDc * NXc];
__device__ float g_WB[NUc * NXc];
__device__ float g_bvec[NXc];
__device__ float g_x0[Bc * NXc];
__device__ float g_C[(size_t)NSTEPSc * Bc * NXc];
__device__ float g_acc[8];

__device__ __forceinline__ float sigmoid_f(float x) { return 1.0f / (1.0f + expf(-x)); }
__device__ __forceinline__ float relu_f(float x) { return fmaxf(x, 0.0f); }
__device__ __forceinline__ float gelu_tanh(float x) {
    float x3 = x * x * x;
    float t = tanhf(0.7978845608028654f * (x + 0.044715f * x3));
    return 0.5f * x * (1.0f + t);
}

// ---------------- kernel 0: zero accumulators --------------------------------
__global__ void k_zero() {
    if (threadIdx.x < 8) g_acc[threadIdx.x] = 0.0f;
}

// ---------------- kernel 1: spectral weights + Gram sums ---------------------
__global__ void __launch_bounds__(128) k_setup(
    const float* __restrict__ UA, const float* __restrict__ sigA, const float* __restrict__ VA,
    const float* __restrict__ UC, const float* __restrict__ sigC, const float* __restrict__ VC)
{
    __shared__ float sA[128], sC[64], rowUA[128], rowUC[64];
    __shared__ float colUA[128], colVA[128], colUC[128], colVC[64];
    __shared__ float red[4];
    int i = blockIdx.x, j = threadIdx.x;

    sA[j] = 0.1f + 0.8f * sigmoid_f(sigA[j]);
    rowUA[j] = UA[i * 128 + j];
    colUA[j] = UA[j * 128 + i];
    colVA[j] = VA[j * 128 + i];
    colUC[j] = UC[j * 128 + i];
    if (j < 64) {
        sC[j] = 0.9f + 0.1f * sigmoid_f(sigC[j]);
        rowUC[j] = UC[i * 128 + j];
        if (i < 64) colVC[j] = VC[j * 64 + i];
    }
    __syncthreads();

    float acc = 0.0f;
    #pragma unroll 8
    for (int k = 0; k < 128; k++) acc = fmaf(rowUA[k] * sA[k], VA[k * 128 + j], acc);
    g_WA[i * 128 + j] = acc;

    if (j < 64) {
        float a = 0.0f;
        #pragma unroll 8
        for (int k = 0; k < 64; k++) a = fmaf(rowUC[k] * sC[k], VC[k * 64 + j], a);
        g_WC[i * 64 + j] = a;
    }

    float gua = 0.0f, gva = 0.0f, guc = 0.0f;
    #pragma unroll 8
    for (int k = 0; k < 128; k++) {
        gua = fmaf(colUA[k], UA[k * 128 + j], gua);
        gva = fmaf(colVA[k], VA[k * 128 + j], gva);
        guc = fmaf(colUC[k], UC[k * 128 + j], guc);
    }
    float p6 = 0.0f, p7 = 0.0f;
    if (i < 64 && j < 64) {
        float g = 0.0f;
        #pragma unroll 8
        for (int k = 0; k < 64; k++) g = fmaf(colVC[k], VC[k * 64 + j], g);
        p6 = g * g;
        float v = VC[i * 64 + j];
        p7 = v * v;
    }
    float part[8];
    part[0] = gua * gua;
    part[1] = rowUA[j] * rowUA[j];
    part[2] = gva * gva;
    { float v = VA[i * 128 + j]; part[3] = v * v; }
    part[4] = guc * guc;
    { float v = UC[i * 128 + j]; part[5] = v * v; }
    part[6] = p6;
    part[7] = p7;

    for (int v = 0; v < 8; v++) {
        float x = part[v];
        #pragma unroll
        for (int o = 16; o; o >>= 1) x += __shfl_xor_sync(0xffffffffu, x, o);
        if ((j & 31) == 0) red[j >> 5] = x;
        __syncthreads();
        if (j == 0) atomicAdd(&g_acc[v], red[0] + red[1] + red[2] + red[3]);
        __syncthreads();
    }
}

// ---------------- kernel 2: W_E, W_B, bvec, SpectErr -------------------------
__global__ void __launch_bounds__(128) k_setup2(
    const float* __restrict__ x0c, const float* __restrict__ wE,
    const float* __restrict__ sE, const float* __restrict__ wB,
    float* __restrict__ out)
{
    __shared__ float xc[128];
    int j = threadIdx.x;
    xc[j] = x0c[j];
    __syncthreads();

    float b = 0.0f;
    #pragma unroll 8
    for (int k = 0; k < 128; k++) b = fmaf(xc[k], g_WA[k * 128 + j], b);
    g_bvec[j] = b;

    float mx = -1e30f;
    for (int i = 0; i < 32; i++) mx = fmaxf(mx, wE[i * 128 + j]);
    float s = 0.0f;
    for (int i = 0; i < 32; i++) s += expf(wE[i * 128 + j] - mx);
    float inv = 1.0f / s;
    for (int i = 0; i < 32; i++) {
        float sm = expf(wE[i * 128 + j] - mx) * inv;
        float sc = 1.0f - 0.95f * sigmoid_f(sE[i * 128 + j]);
        g_WE[i * 128 + j] = sc * sm;
    }
    for (int idx = j; idx < NUc * NXc; idx += 128) g_WB[idx] = relu_f(wB[idx]);

    float errA = (g_acc[0] - 2.0f * g_acc[1] + 128.0f) * (1.0f / 16384.0f)
               + (g_acc[2] - 2.0f * g_acc[3] + 128.0f) * (1.0f / 16384.0f);
    float errC = (g_acc[4] - 2.0f * g_acc[5] + 128.0f) * (1.0f / 16384.0f)
               + (g_acc[6] - 2.0f * g_acc[7] + 64.0f) * (1.0f / 4096.0f);
    float sp = errA + errC;
    for (int idx = j; idx < NSTEPSc; idx += 128) out[OFF_SPECT + idx] = sp;
}

// ---------------- kernel 3: RNN warmup (proven version) ----------------------
__global__ void __launch_bounds__(512) k_rnn(
    const float* __restrict__ Ym, const float* __restrict__ Wih,
    const float* __restrict__ Whh)
{
    __shared__ float h_sh[128];
    __shared__ float ym_sh[2][64];
    __shared__ float p_sh[3 * 128];
    int tid = threadIdx.x;
    int b = blockIdx.x;
    int j = tid & 127, h = tid >> 7;

    float whh_r[32];
    #pragma unroll
    for (int kk = 0; kk < 32; kk++) whh_r[kk] = Whh[(h * 32 + kk) * 128 + j];
    float wih_r[16];
    #pragma unroll
    for (int kk = 0; kk < 16; kk++) wih_r[kk] = Wih[(h * 16 + kk) * 128 + j];

    if (tid < 128) h_sh[tid] = 0.0f;
    if (tid >= 448) ym_sh[0][tid - 448] = Ym[(size_t)b * 64 + (tid - 448)];
    __syncthreads();

    for (int t = 0; t < TPc; t++) {
        const float* yc = ym_sh[t & 1];
        float acc = 0.0f;
        #pragma unroll
        for (int kk = 0; kk < 16; kk++)
            acc = fmaf(yc[h * 16 + kk], wih_r[kk], acc);
        #pragma unroll
        for (int kk = 0; kk < 32; kk++)
            acc = fmaf(h_sh[h * 32 + kk], whh_r[kk], acc);

        if (tid >= 448 && t + 1 < TPc)
            ym_sh[(t + 1) & 1][tid - 448] = Ym[((size_t)(t + 1) * Bc + b) * 64 + (tid - 448)];

        if (h) p_sh[(h - 1) * 128 + j] = acc;
        __syncthreads();
        if (h == 0)
            h_sh[j] = gelu_tanh(acc + p_sh[j] + p_sh[128 + j] + p_sh[256 + j]);
        __syncthreads();
    }
    if (tid < 128) g_x0[b * 128 + tid] = h_sh[tid];
}

// ---------------- kernel 4: precompute (u, Bu, Ed, slacks) -------------------
// 512 threads, one block per t. Whf split 16 ways per output o -> 64 weight
// regs/thread (4 warps/SMSP for latency hiding). Single barrier per sample:
//   S1 computes u(bp) into u[bp&1] from g[bp&1] (all 512 threads);
//   S0 builds g(bp+1) into g[1-(bp&1)] (threads 0..255);
//   S2 drains outputs for bp-1 from u[1-(bp&1)] (threads 0..127 & 384..415).
#define SM_PRE_FLOATS (4096*3 + 4096*2 + 2048 + 64 + 128*3)
__global__ void __launch_bounds__(512) k_pre(
    const float* __restrict__ M, const float* __restrict__ DTin,
    const float* __restrict__ Din, const float* __restrict__ UMIN,
    const float* __restrict__ UMAX, const float* __restrict__ Whf,
    const float* __restrict__ dxmn_g, const float* __restrict__ dxmx_g,
    float* __restrict__ out)
{
    extern __shared__ float sm[];
    float* m_all   = sm;             // 4096
    float* dt_all  = sm + 4096;      // 4096
    float* d_all   = sm + 8192;      // 4096
    float* wb_sh   = sm + 12288;     // 4096
    float* we_sh   = sm + 16384;     // 4096
    float* g2      = sm + 20480;     // 2 x 1024
    float* u_sh    = sm + 22528;     // 2 x 32
    float* bvec_sh = sm + 22592;     // 128
    float* dxmn_sh = sm + 22720;     // 128
    float* dxmx_sh = sm + 22848;     // 128

    int tid = threadIdx.x;
    int t = blockIdx.x;
    int o = tid >> 4, l = tid & 15;
    int lh = l >> 3, lj = l & 7;

    // Whf -> registers: thread (o,l) holds W_hf[o][lh*16+i'][lj*4..lj*4+3], i'=0..15
    float4 w[16];
    const float4* whf4 = (const float4*)Whf;
    #pragma unroll
    for (int i = 0; i < 16; i++)
        w[i] = whf4[(o * 32 + lh * 16 + i) * 8 + lj];

    size_t tb = (size_t)t * 4096;
    {
        const float4* M4  = (const float4*)(M + tb);
        const float4* DT4 = (const float4*)(DTin + tb);
        const float4* D4  = (const float4*)(Din + tb);
        float4* m4  = (float4*)m_all;
        float4* dt4 = (float4*)dt_all;
        float4* d4  = (float4*)d_all;
        #pragma unroll
        for (int idx = tid; idx < 1024; idx += 512) {
            m4[idx] = M4[idx];
            dt4[idx] = DT4[idx];
            d4[idx] = D4[idx];
        }
    }
    for (int idx = tid; idx < 4096; idx += 512) {
        wb_sh[idx] = g_WB[idx];
        we_sh[idx] = g_WE[idx];
    }
    if (tid < 128) {
        bvec_sh[tid] = g_bvec[tid];
        dxmn_sh[tid] = dxmn_g[tid];
        dxmx_sh[tid] = dxmx_g[tid];
    }
    // UMIN/UMAX register ring (threads 384..415), depth 2
    int uo = tid - 384;
    float umnr[2] = {0.f, 0.f}, umxr[2] = {0.f, 0.f};
    if (uo >= 0 && uo < 32) {
        umnr[0] = UMIN[tb + uo];
        umxr[0] = UMAX[tb + uo];
        umnr[1] = UMIN[tb + 32 + uo];
        umxr[1] = UMAX[tb + 32 + uo];
    }
    __syncthreads();
    // build g for b=0
    if (tid < 256) {
        int idx = tid * 4;
        int gi = idx >> 5, gj4 = (idx & 31) >> 2;
        float4 dv = ((const float4*)dt_all)[gj4];
        float mi = m_all[gi];
        ((float4*)g2)[tid] = make_float4(mi * dv.x, mi * dv.y, mi * dv.z, mi * dv.w);
    }
    __syncthreads();

    for (int bp = 0; bp <= 128; bp++) {
        int cur = bp & 1;

        // ---- S1: bilinear u(bp)
        if (bp < 128) {
            const float4* g4 = (const float4*)(g2 + cur * 1024);
            float a0 = 0.0f, a1 = 0.0f;
            #pragma unroll
            for (int i = 0; i < 16; i += 2) {
                float4 gv0 = g4[(lh * 16 + i) * 8 + lj];
                float4 gv1 = g4[(lh * 16 + i + 1) * 8 + lj];
                a0 = fmaf(w[i].x, gv0.x, a0);
                a0 = fmaf(w[i].y, gv0.y, a0);
                a0 = fmaf(w[i].z, gv0.z, a0);
                a0 = fmaf(w[i].w, gv0.w, a0);
                a1 = fmaf(w[i + 1].x, gv1.x, a1);
                a1 = fmaf(w[i + 1].y, gv1.y, a1);
                a1 = fmaf(w[i + 1].z, gv1.z, a1);
                a1 = fmaf(w[i + 1].w, gv1.w, a1);
            }
            float acc = a0 + a1;
            acc += __shfl_xor_sync(0xffffffffu, acc, 1);
            acc += __shfl_xor_sync(0xffffffffu, acc, 2);
            acc += __shfl_xor_sync(0xffffffffu, acc, 4);
            acc += __shfl_xor_sync(0xffffffffu, acc, 8);
            if (l == 0) u_sh[cur * 32 + o] = acc;
        }

        // ---- S0: build g(bp+1)
        if (tid < 256 && bp + 1 < 128) {
            int idx = tid * 4;
            int gi = idx >> 5, gj4 = (idx & 31) >> 2;
            float4 dv = ((const float4*)(dt_all + (bp + 1) * 32))[gj4];
            float mi = m_all[(bp + 1) * 32 + gi];
            ((float4*)(g2 + (1 - cur) * 1024))[tid] =
                make_float4(mi * dv.x, mi * dv.y, mi * dv.z, mi * dv.w);
        }

        // ---- S2: drain outputs for b2 = bp-1
        if (bp >= 1) {
            int b2 = bp - 1;
            int pv = b2 & 1;
            if (tid < 128) {
                float bu = 0.0f, ed = 0.0f;
                #pragma unroll
                for (int oo = 0; oo < 32; oo++) {
                    bu = fmaf(u_sh[pv * 32 + oo], wb_sh[oo * 128 + tid], bu);
                    ed = fmaf(d_all[b2 * 32 + oo], we_sh[oo * 128 + tid], ed);
                }
                size_t base128 = ((size_t)t * Bc + b2) * 128;
                float dn = dxmn_sh[tid], dx = dxmx_sh[tid];
                out[OFF_SDXU + base128 + tid] = relu_f(dn - bu) + relu_f(bu - dx);
                out[OFF_SDXD + base128 + tid] = relu_f(dn - ed) + relu_f(ed - dx);
                g_C[base128 + tid] = bu + ed + bvec_sh[tid];
            } else if (uo >= 0 && uo < 32) {
                float uu = u_sh[pv * 32 + uo];
                size_t base32 = tb + (size_t)b2 * 32;
                out[OFF_U + base32 + uo]     = uu;
                out[OFF_SUMIN + base32 + uo] = relu_f(umnr[pv] - uu);
                out[OFF_SUMAX + base32 + uo] = relu_f(uu - umxr[pv]);
                if (b2 + 2 < 128) {
                    umnr[pv] = UMIN[base32 + 64 + uo];
                    umxr[pv] = UMAX[base32 + 64 + uo];
                }
            }
        }
        __syncthreads();
    }
}

// ---------------- kernel 5: sequential rollout (2014-proven version) ---------
__global__ void __launch_bounds__(512) k_seq(
    const float* __restrict__ XMIN, const float* __restrict__ XMAX,
    const float* __restrict__ Cg, float* __restrict__ out)
{
    __shared__ float x_sh[128];
    __shared__ float p_sh[3 * 128];
    int tid = threadIdx.x;
    int b = blockIdx.x;
    int j = tid & 127, h = tid >> 7;

    float wa[32];
    #pragma unroll
    for (int kk = 0; kk < 32; kk++) wa[kk] = g_WA[(h * 32 + kk) * 128 + j];

    if (tid < 128) x_sh[tid] = g_x0[b * 128 + tid];

    float c0 = 0, c1 = 0, mn0 = 0, mn1 = 0, mx0 = 0, mx1 = 0;
    if (h == 0) {
        size_t i0 = ((size_t)0 * Bc + b) * 128 + j;
        size_t i1 = ((size_t)1 * Bc + b) * 128 + j;
        c0 = Cg[i0]; mn0 = XMIN[i0]; mx0 = XMAX[i0];
        c1 = Cg[i1]; mn1 = XMIN[i1]; mx1 = XMAX[i1];
    }
    __syncthreads();

    for (int t = 0; t < NSTEPSc; t++) {
        float acc = 0.0f;
        const float4* x4 = ((const float4*)x_sh) + h * 8;
        #pragma unroll
        for (int kk = 0; kk < 8; kk++) {
            float4 xv = x4[kk];
            acc = fmaf(xv.x, wa[kk * 4 + 0], acc);
            acc = fmaf(xv.y, wa[kk * 4 + 1], acc);
            acc = fmaf(xv.z, wa[kk * 4 + 2], acc);
            acc = fmaf(xv.w, wa[kk * 4 + 3], acc);
        }
        // prefetch t+2
        float cn = 0, mnn = 0, mxn = 0;
        if (h == 0 && t + 2 < NSTEPSc) {
            size_t i2 = ((size_t)(t + 2) * Bc + b) * 128 + j;
            cn = Cg[i2]; mnn = XMIN[i2]; mxn = XMAX[i2];
        }
        if (h) p_sh[(h - 1) * 128 + j] = acc;
        __syncthreads();

        if (h == 0) {
            float xold = x_sh[j];
            float xn = acc + p_sh[j] + p_sh[128 + j] + p_sh[256 + j] + c0;
            size_t bi = ((size_t)t * Bc + b) * 128 + j;
            out[OFF_X + bi]     = xn;
            out[OFF_SXMIN + bi] = relu_f(mn0 - xn);
            out[OFF_SXMAX + bi] = relu_f(xn - mx0);
            out[OFF_SDXX + bi]  = xn - xold;
            x_sh[j] = xn;
            c0 = c1; mn0 = mn1; mx0 = mx1;
            c1 = cn; mn1 = mnn; mx1 = mxn;
        }
        __syncthreads();
    }
}

// ---------------- kernel 6: Y = X @ W_C (64 rows/block, weights amortized) ---
__global__ void __launch_bounds__(256) k_post(float* __restrict__ out)
{
    __shared__ float xs[64 * 128];   // 32 KB
    int tid = threadIdx.x;
    size_t row0 = (size_t)blockIdx.x * 64;
    int r0 = tid >> 6, j2 = tid & 63;

    float wc[128];
    #pragma unroll
    for (int kk = 0; kk < 128; kk++) wc[kk] = g_WC[kk * 64 + j2];

    const float4* src = (const float4*)(out + OFF_X + row0 * 128);
    float4* dst4 = (float4*)xs;
    #pragma unroll
    for (int i = 0; i < 8; i++) dst4[tid + i * 256] = src[tid + i * 256];
    __syncthreads();

    #pragma unroll 4
    for (int it = 0; it < 16; it++) {
        int row = it * 4 + r0;
        const float* xr = xs + row * 128;
        float a0 = 0.0f, a1 = 0.0f;
        #pragma unroll
        for (int kk = 0; kk < 64; kk++) {
            a0 = fmaf(xr[kk],      wc[kk],      a0);
            a1 = fmaf(xr[64 + kk], wc[64 + kk], a1);
        }
        out[OFF_Y + (row0 + row) * 64 + j2] = a0 + a1;
    }
}

// ---------------- launch ------------------------------------------------------
extern "C" void kernel_launch(void* const* d_in, const int* in_sizes, int n_in,
                              void* d_out, int out_size)
{
    const float* Ym   = (const float*)d_in[0];
    const float* M    = (const float*)d_in[1];
    const float* DTin = (const float*)d_in[2];
    const float* Din  = (const float*)d_in[3];
    const float* XMIN = (const float*)d_in[4];
    const float* XMAX = (const float*)d_in[5];
    const float* UMIN = (const float*)d_in[6];
    const float* UMAX = (const float*)d_in[7];
    const float* x0c  = (const float*)d_in[8];
    const float* UA   = (const float*)d_in[9];
    const float* sigA = (const float*)d_in[10];
    const float* VA   = (const float*)d_in[11];
    const float* UC   = (const float*)d_in[12];
    const float* sigC = (const float*)d_in[13];
    const float* VC   = (const float*)d_in[14];
    const float* wE   = (const float*)d_in[15];
    const float* sE   = (const float*)d_in[16];
    const float* wB   = (const float*)d_in[17];
    const float* Whf  = (const float*)d_in[18];
    const float* Wih  = (const float*)d_in[19];
    const float* Whh  = (const float*)d_in[20];
    const float* dxmn = (const float*)d_in[21];
    const float* dxmx = (const float*)d_in[22];
    float* out = (float*)d_out;

    static const size_t smem_pre = SM_PRE_FLOATS * sizeof(float);
    cudaFuncSetAttribute(k_pre, cudaFuncAttributeMaxDynamicSharedMemorySize,
                         (int)smem_pre);

    float* Cg = nullptr;
    cudaGetSymbolAddress((void**)&Cg, g_C);

    // k_pre moved to the 4th slot (position ncu has been capturing).
    k_zero<<<1, 32>>>();
    k_setup<<<128, 128>>>(UA, sigA, VA, UC, sigC, VC);
    k_setup2<<<1, 128>>>(x0c, wE, sE, wB, out);
    k_pre<<<NSTEPSc, 512, smem_pre>>>(M, DTin, Din, UMIN, UMAX, Whf, dxmn, dxmx, out);
    k_rnn<<<Bc, 512>>>(Ym, Wih, Whh);
    k_seq<<<Bc, 512>>>(XMIN, XMAX, Cg, out);
    k_post<<<(NSTEPSc * Bc) / 64, 256>>>(out);
}

// round 7
// speedup vs baseline: 1.8522x; 1.0735x over previous
#include <cuda_runtime.h>
#include <math.h>

// Problem dims
#define NXc 128
#define NYc 64
#define NMc 32
#define NDTc 32
#define NUc 32
#define NDc 32
#define NSTEPSc 1024
#define Bc 128
#define TPc 64

// Output offsets (floats) for the flattened 11-tuple
#define OFF_X      ((size_t)0)
#define OFF_Y      ((size_t)16777216)
#define OFF_U      ((size_t)25165824)
#define OFF_SXMIN  ((size_t)29360128)
#define OFF_SXMAX  ((size_t)46137344)
#define OFF_SUMIN  ((size_t)62914560)
#define OFF_SUMAX  ((size_t)67108864)
#define OFF_SDXX   ((size_t)71303168)
#define OFF_SDXU   ((size_t)88080384)
#define OFF_SDXD   ((size_t)104857600)
#define OFF_SPECT  ((size_t)121634816)

// ---------------- module-scope scratch ----------------
__device__ float g_WA[NXc * NXc];
__device__ float g_WC[NXc * NYc];
__device__ float g_WE[NDc * NXc];
__device__ float g_WB[NUc * NXc];
__device__ float g_bvec[NXc];
__device__ float g_x0[Bc * NXc];
__device__ float g_C[(size_t)NSTEPSc * Bc * NXc];
__device__ float g_acc[8];

__device__ __forceinline__ float sigmoid_f(float x) { return 1.0f / (1.0f + expf(-x)); }
__device__ __forceinline__ float relu_f(float x) { return fmaxf(x, 0.0f); }
__device__ __forceinline__ float gelu_tanh(float x) {
    float x3 = x * x * x;
    float t = tanhf(0.7978845608028654f * (x + 0.044715f * x3));
    return 0.5f * x * (1.0f + t);
}

// ---------------- kernel 0: zero accumulators --------------------------------
__global__ void k_zero() {
    if (threadIdx.x < 8) g_acc[threadIdx.x] = 0.0f;
}

// ---------------- kernel 1: spectral weights + Gram sums ---------------------
__global__ void __launch_bounds__(128) k_setup(
    const float* __restrict__ UA, const float* __restrict__ sigA, const float* __restrict__ VA,
    const float* __restrict__ UC, const float* __restrict__ sigC, const float* __restrict__ VC)
{
    __shared__ float sA[128], sC[64], rowUA[128], rowUC[64];
    __shared__ float colUA[128], colVA[128], colUC[128], colVC[64];
    __shared__ float red[4];
    int i = blockIdx.x, j = threadIdx.x;

    sA[j] = 0.1f + 0.8f * sigmoid_f(sigA[j]);
    rowUA[j] = UA[i * 128 + j];
    colUA[j] = UA[j * 128 + i];
    colVA[j] = VA[j * 128 + i];
    colUC[j] = UC[j * 128 + i];
    if (j < 64) {
        sC[j] = 0.9f + 0.1f * sigmoid_f(sigC[j]);
        rowUC[j] = UC[i * 128 + j];
        if (i < 64) colVC[j] = VC[j * 64 + i];
    }
    __syncthreads();

    float acc = 0.0f;
    #pragma unroll 8
    for (int k = 0; k < 128; k++) acc = fmaf(rowUA[k] * sA[k], VA[k * 128 + j], acc);
    g_WA[i * 128 + j] = acc;

    if (j < 64) {
        float a = 0.0f;
        #pragma unroll 8
        for (int k = 0; k < 64; k++) a = fmaf(rowUC[k] * sC[k], VC[k * 64 + j], a);
        g_WC[i * 64 + j] = a;
    }

    float gua = 0.0f, gva = 0.0f, guc = 0.0f;
    #pragma unroll 8
    for (int k = 0; k < 128; k++) {
        gua = fmaf(colUA[k], UA[k * 128 + j], gua);
        gva = fmaf(colVA[k], VA[k * 128 + j], gva);
        guc = fmaf(colUC[k], UC[k * 128 + j], guc);
    }
    float p6 = 0.0f, p7 = 0.0f;
    if (i < 64 && j < 64) {
        float g = 0.0f;
        #pragma unroll 8
        for (int k = 0; k < 64; k++) g = fmaf(colVC[k], VC[k * 64 + j], g);
        p6 = g * g;
        float v = VC[i * 64 + j];
        p7 = v * v;
    }
    float part[8];
    part[0] = gua * gua;
    part[1] = rowUA[j] * rowUA[j];
    part[2] = gva * gva;
    { float v = VA[i * 128 + j]; part[3] = v * v; }
    part[4] = guc * guc;
    { float v = UC[i * 128 + j]; part[5] = v * v; }
    part[6] = p6;
    part[7] = p7;

    for (int v = 0; v < 8; v++) {
        float x = part[v];
        #pragma unroll
        for (int o = 16; o; o >>= 1) x += __shfl_xor_sync(0xffffffffu, x, o);
        if ((j & 31) == 0) red[j >> 5] = x;
        __syncthreads();
        if (j == 0) atomicAdd(&g_acc[v], red[0] + red[1] + red[2] + red[3]);
        __syncthreads();
    }
}

// ---------------- kernel 2: W_E, W_B, bvec, SpectErr -------------------------
__global__ void __launch_bounds__(128) k_setup2(
    const float* __restrict__ x0c, const float* __restrict__ wE,
    const float* __restrict__ sE, const float* __restrict__ wB,
    float* __restrict__ out)
{
    __shared__ float xc[128];
    int j = threadIdx.x;
    xc[j] = x0c[j];
    __syncthreads();

    float b = 0.0f;
    #pragma unroll 8
    for (int k = 0; k < 128; k++) b = fmaf(xc[k], g_WA[k * 128 + j], b);
    g_bvec[j] = b;

    float mx = -1e30f;
    for (int i = 0; i < 32; i++) mx = fmaxf(mx, wE[i * 128 + j]);
    float s = 0.0f;
    for (int i = 0; i < 32; i++) s += expf(wE[i * 128 + j] - mx);
    float inv = 1.0f / s;
    for (int i = 0; i < 32; i++) {
        float sm = expf(wE[i * 128 + j] - mx) * inv;
        float sc = 1.0f - 0.95f * sigmoid_f(sE[i * 128 + j]);
        g_WE[i * 128 + j] = sc * sm;
    }
    for (int idx = j; idx < NUc * NXc; idx += 128) g_WB[idx] = relu_f(wB[idx]);

    float errA = (g_acc[0] - 2.0f * g_acc[1] + 128.0f) * (1.0f / 16384.0f)
               + (g_acc[2] - 2.0f * g_acc[3] + 128.0f) * (1.0f / 16384.0f);
    float errC = (g_acc[4] - 2.0f * g_acc[5] + 128.0f) * (1.0f / 16384.0f)
               + (g_acc[6] - 2.0f * g_acc[7] + 64.0f) * (1.0f / 4096.0f);
    float sp = errA + errC;
    for (int idx = j; idx < NSTEPSc; idx += 128) out[OFF_SPECT + idx] = sp;
}

// ---------------- kernel 3: RNN warmup (proven version) ----------------------
__global__ void __launch_bounds__(512) k_rnn(
    const float* __restrict__ Ym, const float* __restrict__ Wih,
    const float* __restrict__ Whh)
{
    __shared__ float h_sh[128];
    __shared__ float ym_sh[2][64];
    __shared__ float p_sh[3 * 128];
    int tid = threadIdx.x;
    int b = blockIdx.x;
    int j = tid & 127, h = tid >> 7;

    float whh_r[32];
    #pragma unroll
    for (int kk = 0; kk < 32; kk++) whh_r[kk] = Whh[(h * 32 + kk) * 128 + j];
    float wih_r[16];
    #pragma unroll
    for (int kk = 0; kk < 16; kk++) wih_r[kk] = Wih[(h * 16 + kk) * 128 + j];

    if (tid < 128) h_sh[tid] = 0.0f;
    if (tid >= 448) ym_sh[0][tid - 448] = Ym[(size_t)b * 64 + (tid - 448)];
    __syncthreads();

    for (int t = 0; t < TPc; t++) {
        const float* yc = ym_sh[t & 1];
        float acc = 0.0f;
        #pragma unroll
        for (int kk = 0; kk < 16; kk++)
            acc = fmaf(yc[h * 16 + kk], wih_r[kk], acc);
        #pragma unroll
        for (int kk = 0; kk < 32; kk++)
            acc = fmaf(h_sh[h * 32 + kk], whh_r[kk], acc);

        if (tid >= 448 && t + 1 < TPc)
            ym_sh[(t + 1) & 1][tid - 448] = Ym[((size_t)(t + 1) * Bc + b) * 64 + (tid - 448)];

        if (h) p_sh[(h - 1) * 128 + j] = acc;
        __syncthreads();
        if (h == 0)
            h_sh[j] = gelu_tanh(acc + p_sh[j] + p_sh[128 + j] + p_sh[256 + j]);
        __syncthreads();
    }
    if (tid < 128) g_x0[b * 128 + tid] = h_sh[tid];
}

// ---------------- kernel 4: precompute (u, Bu, Ed, slacks) -------------------
// Factorized bilinear: u[o] = sum_i m_i * (sum_j W[o,i,j] dT_j) — g is never
// materialized, killing the smem-pipe bottleneck (L1 59.5% in R6 profile).
// 512 threads, Whf split 16 ways (w[16] float4). Single barrier per sample:
//   S1 computes u(bp) into u[bp&1]; S2 drains outputs for bp-1 from u[1-(bp&1)].
#define SM_PRE_FLOATS (4096*3 + 4096*2 + 64 + 128*3)
__global__ void __launch_bounds__(512) k_pre(
    const float* __restrict__ M, const float* __restrict__ DTin,
    const float* __restrict__ Din, const float* __restrict__ UMIN,
    const float* __restrict__ UMAX, const float* __restrict__ Whf,
    const float* __restrict__ dxmn_g, const float* __restrict__ dxmx_g,
    float* __restrict__ out)
{
    extern __shared__ float sm[];
    float* m_all   = sm;             // 4096
    float* dt_all  = sm + 4096;      // 4096
    float* d_all   = sm + 8192;      // 4096
    float* wb_sh   = sm + 12288;     // 4096
    float* we_sh   = sm + 16384;     // 4096
    float* u_sh    = sm + 20480;     // 2 x 32
    float* bvec_sh = sm + 20544;     // 128
    float* dxmn_sh = sm + 20672;     // 128
    float* dxmx_sh = sm + 20800;     // 128

    int tid = threadIdx.x;
    int t = blockIdx.x;
    int o = tid >> 4, l = tid & 15;
    int lh = l >> 3, lj = l & 7;

    // Whf -> registers: thread (o,l) holds W_hf[o][lh*16+i][lj*4..lj*4+3]
    float4 w[16];
    const float4* whf4 = (const float4*)Whf;
    #pragma unroll
    for (int i = 0; i < 16; i++)
        w[i] = whf4[(o * 32 + lh * 16 + i) * 8 + lj];

    size_t tb = (size_t)t * 4096;
    {
        const float4* M4  = (const float4*)(M + tb);
        const float4* DT4 = (const float4*)(DTin + tb);
        const float4* D4  = (const float4*)(Din + tb);
        float4* m4  = (float4*)m_all;
        float4* dt4 = (float4*)dt_all;
        float4* d4  = (float4*)d_all;
        #pragma unroll
        for (int idx = tid; idx < 1024; idx += 512) {
            m4[idx] = M4[idx];
            dt4[idx] = DT4[idx];
            d4[idx] = D4[idx];
        }
    }
    for (int idx = tid; idx < 4096; idx += 512) {
        wb_sh[idx] = g_WB[idx];
        we_sh[idx] = g_WE[idx];
    }
    if (tid < 128) {
        bvec_sh[tid] = g_bvec[tid];
        dxmn_sh[tid] = dxmn_g[tid];
        dxmx_sh[tid] = dxmx_g[tid];
    }
    // UMIN/UMAX register ring (threads 384..415), depth 2
    int uo = tid - 384;
    float umnr[2] = {0.f, 0.f}, umxr[2] = {0.f, 0.f};
    if (uo >= 0 && uo < 32) {
        umnr[0] = UMIN[tb + uo];
        umxr[0] = UMAX[tb + uo];
        umnr[1] = UMIN[tb + 32 + uo];
        umxr[1] = UMAX[tb + 32 + uo];
    }
    __syncthreads();

    for (int bp = 0; bp <= 128; bp++) {
        int cur = bp & 1;

        // ---- S1: factorized bilinear u(bp)
        if (bp < 128) {
            float4 dtv = ((const float4*)(dt_all + bp * 32))[lj];
            const float* mrow = m_all + bp * 32 + lh * 16;
            float acc = 0.0f;
            #pragma unroll
            for (int i = 0; i < 16; i++) {
                float p = w[i].x * dtv.x;
                p = fmaf(w[i].y, dtv.y, p);
                p = fmaf(w[i].z, dtv.z, p);
                p = fmaf(w[i].w, dtv.w, p);
                acc = fmaf(mrow[i], p, acc);
            }
            acc += __shfl_xor_sync(0xffffffffu, acc, 1);
            acc += __shfl_xor_sync(0xffffffffu, acc, 2);
            acc += __shfl_xor_sync(0xffffffffu, acc, 4);
            acc += __shfl_xor_sync(0xffffffffu, acc, 8);
            if (l == 0) u_sh[cur * 32 + o] = acc;
        }

        // ---- S2: drain outputs for b2 = bp-1
        if (bp >= 1) {
            int b2 = bp - 1;
            int pv = b2 & 1;
            if (tid < 128) {
                float bu = 0.0f, ed = 0.0f;
                #pragma unroll
                for (int oo = 0; oo < 32; oo++) {
                    bu = fmaf(u_sh[pv * 32 + oo], wb_sh[oo * 128 + tid], bu);
                    ed = fmaf(d_all[b2 * 32 + oo], we_sh[oo * 128 + tid], ed);
                }
                size_t base128 = ((size_t)t * Bc + b2) * 128;
                float dn = dxmn_sh[tid], dx = dxmx_sh[tid];
                out[OFF_SDXU + base128 + tid] = relu_f(dn - bu) + relu_f(bu - dx);
                out[OFF_SDXD + base128 + tid] = relu_f(dn - ed) + relu_f(ed - dx);
                g_C[base128 + tid] = bu + ed + bvec_sh[tid];
            } else if (uo >= 0 && uo < 32) {
                float uu = u_sh[pv * 32 + uo];
                size_t base32 = tb + (size_t)b2 * 32;
                out[OFF_U + base32 + uo]     = uu;
                out[OFF_SUMIN + base32 + uo] = relu_f(umnr[pv] - uu);
                out[OFF_SUMAX + base32 + uo] = relu_f(uu - umxr[pv]);
                if (b2 + 2 < 128) {
                    umnr[pv] = UMIN[base32 + 64 + uo];
                    umxr[pv] = UMAX[base32 + 64 + uo];
                }
            }
        }
        __syncthreads();
    }
}

// ---------------- kernel 5: sequential rollout -------------------------------
// 128 threads/block; thread j owns column j with ALL 128 W_A weights in
// registers. Double-buffered x -> ONE barrier per step, no reduce round-trip.
__global__ void __launch_bounds__(128) k_seq(
    const float* __restrict__ XMIN, const float* __restrict__ XMAX,
    const float* __restrict__ Cg, float* __restrict__ out)
{
    __shared__ float xbuf[2][128];
    int j = threadIdx.x;
    int b = blockIdx.x;

    float wa[128];
    #pragma unroll
    for (int kk = 0; kk < 128; kk++) wa[kk] = g_WA[kk * 128 + j];

    float xprev = g_x0[b * 128 + j];
    xbuf[0][j] = xprev;

    float c0, c1, mn0, mn1, mx0, mx1;
    {
        size_t i0 = ((size_t)0 * Bc + b) * 128 + j;
        size_t i1 = ((size_t)1 * Bc + b) * 128 + j;
        c0 = Cg[i0]; mn0 = XMIN[i0]; mx0 = XMAX[i0];
        c1 = Cg[i1]; mn1 = XMIN[i1]; mx1 = XMAX[i1];
    }
    __syncthreads();

    for (int t = 0; t < NSTEPSc; t++) {
        int cur = t & 1;
        float a0 = 0.0f, a1 = 0.0f, a2 = 0.0f, a3 = 0.0f;
        const float4* x4 = (const float4*)xbuf[cur];
        #pragma unroll
        for (int kk = 0; kk < 32; kk++) {
            float4 xv = x4[kk];
            a0 = fmaf(xv.x, wa[kk * 4 + 0], a0);
            a1 = fmaf(xv.y, wa[kk * 4 + 1], a1);
            a2 = fmaf(xv.z, wa[kk * 4 + 2], a2);
            a3 = fmaf(xv.w, wa[kk * 4 + 3], a3);
        }
        float xn = (a0 + a1) + (a2 + a3) + c0;
        xbuf[1 - cur][j] = xn;

        // prefetch t+2
        float cn = 0.0f, mnn = 0.0f, mxn = 0.0f;
        if (t + 2 < NSTEPSc) {
            size_t i2 = ((size_t)(t + 2) * Bc + b) * 128 + j;
            cn = Cg[i2]; mnn = XMIN[i2]; mxn = XMAX[i2];
        }

        size_t bi = ((size_t)t * Bc + b) * 128 + j;
        out[OFF_X + bi]     = xn;
        out[OFF_SXMIN + bi] = relu_f(mn0 - xn);
        out[OFF_SXMAX + bi] = relu_f(xn - mx0);
        out[OFF_SDXX + bi]  = xn - xprev;
        xprev = xn;
        c0 = c1; mn0 = mn1; mx0 = mx1;
        c1 = cn; mn1 = mnn; mx1 = mxn;
        __syncthreads();
    }
}

// ---------------- kernel 6: Y = X @ W_C (2-row version from 2014-us run) -----
__global__ void __launch_bounds__(256) k_post(float* __restrict__ out)
{
    __shared__ float x2[256];
    __shared__ float p2[128];
    int tid = threadIdx.x;
    size_t row0 = (size_t)blockIdx.x * 2;
    int r = tid >> 7;
    int q = (tid >> 6) & 1, j2 = tid & 63;

    float wc[64];
    #pragma unroll
    for (int kk = 0; kk < 64; kk++) wc[kk] = g_WC[(q * 64 + kk) * 64 + j2];

    x2[tid] = out[OFF_X + row0 * 128 + tid];
    __syncthreads();

    float part = 0.0f;
    const float* xr = x2 + r * 128 + q * 64;
    #pragma unroll
    for (int kk = 0; kk < 64; kk++) part = fmaf(xr[kk], wc[kk], part);

    if (q == 1) p2[r * 64 + j2] = part;
    __syncthreads();
    if (q == 0)
        out[OFF_Y + row0 * 64 + (size_t)r * 64 + j2] = part + p2[r * 64 + j2];
}

// ---------------- launch ------------------------------------------------------
extern "C" void kernel_launch(void* const* d_in, const int* in_sizes, int n_in,
                              void* d_out, int out_size)
{
    const float* Ym   = (const float*)d_in[0];
    const float* M    = (const float*)d_in[1];
    const float* DTin = (const float*)d_in[2];
    const float* Din  = (const float*)d_in[3];
    const float* XMIN = (const float*)d_in[4];
    const float* XMAX = (const float*)d_in[5];
    const float* UMIN = (const float*)d_in[6];
    const float* UMAX = (const float*)d_in[7];
    const float* x0c  = (const float*)d_in[8];
    const float* UA   = (const float*)d_in[9];
    const float* sigA = (const float*)d_in[10];
    const float* VA   = (const float*)d_in[11];
    const float* UC   = (const float*)d_in[12];
    const float* sigC = (const float*)d_in[13];
    const float* VC   = (const float*)d_in[14];
    const float* wE   = (const float*)d_in[15];
    const float* sE   = (const float*)d_in[16];
    const float* wB   = (const float*)d_in[17];
    const float* Whf  = (const float*)d_in[18];
    const float* Wih  = (const float*)d_in[19];
    const float* Whh  = (const float*)d_in[20];
    const float* dxmn = (const float*)d_in[21];
    const float* dxmx = (const float*)d_in[22];
    float* out = (float*)d_out;

    static const size_t smem_pre = SM_PRE_FLOATS * sizeof(float);
    cudaFuncSetAttribute(k_pre, cudaFuncAttributeMaxDynamicSharedMemorySize,
                         (int)smem_pre);

    float* Cg = nullptr;
    cudaGetSymbolAddress((void**)&Cg, g_C);

    // k_pre at idx 3 (the slot ncu captures) to verify the L1->fma shift.
    k_zero<<<1, 32>>>();
    k_setup<<<128, 128>>>(UA, sigA, VA, UC, sigC, VC);
    k_setup2<<<1, 128>>>(x0c, wE, sE, wB, out);
    k_pre<<<NSTEPSc, 512, smem_pre>>>(M, DTin, Din, UMIN, UMAX, Whf, dxmn, dxmx, out);
    k_rnn<<<Bc, 512>>>(Ym, Wih, Whh);
    k_seq<<<Bc, 128>>>(XMIN, XMAX, Cg, out);
    k_post<<<(NSTEPSc * Bc) / 2, 256>>>(out);
}

// round 8
// speedup vs baseline: 2.5049x; 1.3523x over previous
#include <cuda_runtime.h>
#include <math.h>

// Problem dims
#define NXc 128
#define NYc 64
#define NMc 32
#define NDTc 32
#define NUc 32
#define NDc 32
#define NSTEPSc 1024
#define Bc 128
#define TPc 64

// Output offsets (floats) for the flattened 11-tuple
#define OFF_X      ((size_t)0)
#define OFF_Y      ((size_t)16777216)
#define OFF_U      ((size_t)25165824)
#define OFF_SXMIN  ((size_t)29360128)
#define OFF_SXMAX  ((size_t)46137344)
#define OFF_SUMIN  ((size_t)62914560)
#define OFF_SUMAX  ((size_t)67108864)
#define OFF_SDXX   ((size_t)71303168)
#define OFF_SDXU   ((size_t)88080384)
#define OFF_SDXD   ((size_t)104857600)
#define OFF_SPECT  ((size_t)121634816)

// ---------------- module-scope scratch ----------------
__device__ float g_WA[NXc * NXc];
__device__ float g_WC[NXc * NYc];
__device__ float g_WE[NDc * NXc];
__device__ float g_WB[NUc * NXc];
__device__ float g_bvec[NXc];
__device__ float g_x0[Bc * NXc];
__device__ float g_C[(size_t)NSTEPSc * Bc * NXc];
__device__ float g_acc[8];

__device__ __forceinline__ float sigmoid_f(float x) { return 1.0f / (1.0f + expf(-x)); }
__device__ __forceinline__ float relu_f(float x) { return fmaxf(x, 0.0f); }
__device__ __forceinline__ float gelu_tanh(float x) {
    float x3 = x * x * x;
    float t = tanhf(0.7978845608028654f * (x + 0.044715f * x3));
    return 0.5f * x * (1.0f + t);
}

// ---------------- kernel 0: zero accumulators --------------------------------
__global__ void k_zero() {
    if (threadIdx.x < 8) g_acc[threadIdx.x] = 0.0f;
}

// ---------------- kernel 1: spectral weights + Gram sums ---------------------
__global__ void __launch_bounds__(128) k_setup(
    const float* __restrict__ UA, const float* __restrict__ sigA, const float* __restrict__ VA,
    const float* __restrict__ UC, const float* __restrict__ sigC, const float* __restrict__ VC)
{
    __shared__ float sA[128], sC[64], rowUA[128], rowUC[64];
    __shared__ float colUA[128], colVA[128], colUC[128], colVC[64];
    __shared__ float red[4];
    int i = blockIdx.x, j = threadIdx.x;

    sA[j] = 0.1f + 0.8f * sigmoid_f(sigA[j]);
    rowUA[j] = UA[i * 128 + j];
    colUA[j] = UA[j * 128 + i];
    colVA[j] = VA[j * 128 + i];
    colUC[j] = UC[j * 128 + i];
    if (j < 64) {
        sC[j] = 0.9f + 0.1f * sigmoid_f(sigC[j]);
        rowUC[j] = UC[i * 128 + j];
        if (i < 64) colVC[j] = VC[j * 64 + i];
    }
    __syncthreads();

    float acc = 0.0f;
    #pragma unroll 8
    for (int k = 0; k < 128; k++) acc = fmaf(rowUA[k] * sA[k], VA[k * 128 + j], acc);
    g_WA[i * 128 + j] = acc;

    if (j < 64) {
        float a = 0.0f;
        #pragma unroll 8
        for (int k = 0; k < 64; k++) a = fmaf(rowUC[k] * sC[k], VC[k * 64 + j], a);
        g_WC[i * 64 + j] = a;
    }

    float gua = 0.0f, gva = 0.0f, guc = 0.0f;
    #pragma unroll 8
    for (int k = 0; k < 128; k++) {
        gua = fmaf(colUA[k], UA[k * 128 + j], gua);
        gva = fmaf(colVA[k], VA[k * 128 + j], gva);
        guc = fmaf(colUC[k], UC[k * 128 + j], guc);
    }
    float p6 = 0.0f, p7 = 0.0f;
    if (i < 64 && j < 64) {
        float g = 0.0f;
        #pragma unroll 8
        for (int k = 0; k < 64; k++) g = fmaf(colVC[k], VC[k * 64 + j], g);
        p6 = g * g;
        float v = VC[i * 64 + j];
        p7 = v * v;
    }
    float part[8];
    part[0] = gua * gua;
    part[1] = rowUA[j] * rowUA[j];
    part[2] = gva * gva;
    { float v = VA[i * 128 + j]; part[3] = v * v; }
    part[4] = guc * guc;
    { float v = UC[i * 128 + j]; part[5] = v * v; }
    part[6] = p6;
    part[7] = p7;

    for (int v = 0; v < 8; v++) {
        float x = part[v];
        #pragma unroll
        for (int o = 16; o; o >>= 1) x += __shfl_xor_sync(0xffffffffu, x, o);
        if ((j & 31) == 0) red[j >> 5] = x;
        __syncthreads();
        if (j == 0) atomicAdd(&g_acc[v], red[0] + red[1] + red[2] + red[3]);
        __syncthreads();
    }
}

// ---------------- kernel 2: W_E, W_B, bvec, SpectErr -------------------------
__global__ void __launch_bounds__(128) k_setup2(
    const float* __restrict__ x0c, const float* __restrict__ wE,
    const float* __restrict__ sE, const float* __restrict__ wB,
    float* __restrict__ out)
{
    __shared__ float xc[128];
    int j = threadIdx.x;
    xc[j] = x0c[j];
    __syncthreads();

    float b = 0.0f;
    #pragma unroll 8
    for (int k = 0; k < 128; k++) b = fmaf(xc[k], g_WA[k * 128 + j], b);
    g_bvec[j] = b;

    float mx = -1e30f;
    for (int i = 0; i < 32; i++) mx = fmaxf(mx, wE[i * 128 + j]);
    float s = 0.0f;
    for (int i = 0; i < 32; i++) s += expf(wE[i * 128 + j] - mx);
    float inv = 1.0f / s;
    for (int i = 0; i < 32; i++) {
        float sm = expf(wE[i * 128 + j] - mx) * inv;
        float sc = 1.0f - 0.95f * sigmoid_f(sE[i * 128 + j]);
        g_WE[i * 128 + j] = sc * sm;
    }
    for (int idx = j; idx < NUc * NXc; idx += 128) g_WB[idx] = relu_f(wB[idx]);

    float errA = (g_acc[0] - 2.0f * g_acc[1] + 128.0f) * (1.0f / 16384.0f)
               + (g_acc[2] - 2.0f * g_acc[3] + 128.0f) * (1.0f / 16384.0f);
    float errC = (g_acc[4] - 2.0f * g_acc[5] + 128.0f) * (1.0f / 16384.0f)
               + (g_acc[6] - 2.0f * g_acc[7] + 64.0f) * (1.0f / 4096.0f);
    float sp = errA + errC;
    for (int idx = j; idx < NSTEPSc; idx += 128) out[OFF_SPECT + idx] = sp;
}

// ---------------- kernel 3: RNN warmup (proven version) ----------------------
__global__ void __launch_bounds__(512) k_rnn(
    const float* __restrict__ Ym, const float* __restrict__ Wih,
    const float* __restrict__ Whh)
{
    __shared__ float h_sh[128];
    __shared__ float ym_sh[2][64];
    __shared__ float p_sh[3 * 128];
    int tid = threadIdx.x;
    int b = blockIdx.x;
    int j = tid & 127, h = tid >> 7;

    float whh_r[32];
    #pragma unroll
    for (int kk = 0; kk < 32; kk++) whh_r[kk] = Whh[(h * 32 + kk) * 128 + j];
    float wih_r[16];
    #pragma unroll
    for (int kk = 0; kk < 16; kk++) wih_r[kk] = Wih[(h * 16 + kk) * 128 + j];

    if (tid < 128) h_sh[tid] = 0.0f;
    if (tid >= 448) ym_sh[0][tid - 448] = Ym[(size_t)b * 64 + (tid - 448)];
    __syncthreads();

    for (int t = 0; t < TPc; t++) {
        const float* yc = ym_sh[t & 1];
        float acc = 0.0f;
        #pragma unroll
        for (int kk = 0; kk < 16; kk++)
            acc = fmaf(yc[h * 16 + kk], wih_r[kk], acc);
        #pragma unroll
        for (int kk = 0; kk < 32; kk++)
            acc = fmaf(h_sh[h * 32 + kk], whh_r[kk], acc);

        if (tid >= 448 && t + 1 < TPc)
            ym_sh[(t + 1) & 1][tid - 448] = Ym[((size_t)(t + 1) * Bc + b) * 64 + (tid - 448)];

        if (h) p_sh[(h - 1) * 128 + j] = acc;
        __syncthreads();
        if (h == 0)
            h_sh[j] = gelu_tanh(acc + p_sh[j] + p_sh[128 + j] + p_sh[256 + j]);
        __syncthreads();
    }
    if (tid < 128) g_x0[b * 128 + tid] = h_sh[tid];
}

// ---------------- kernel 4: precompute, 4-sample batched ---------------------
// Factorized bilinear, 4 samples per barrier-iteration (4 independent FMA
// chains pipeline the issue; barriers 129 -> 33). S2 drains the previous
// group of 4 with 8 interleaved chains.
#define SM_PRE_FLOATS (4096*3 + 4096*2 + 256 + 128*3)
__global__ void __launch_bounds__(512) k_pre(
    const float* __restrict__ M, const float* __restrict__ DTin,
    const float* __restrict__ Din, const float* __restrict__ UMIN,
    const float* __restrict__ UMAX, const float* __restrict__ Whf,
    const float* __restrict__ dxmn_g, const float* __restrict__ dxmx_g,
    float* __restrict__ out)
{
    extern __shared__ float sm[];
    float* m_all   = sm;             // 4096
    float* dt_all  = sm + 4096;      // 4096
    float* d_all   = sm + 8192;      // 4096
    float* wb_sh   = sm + 12288;     // 4096
    float* we_sh   = sm + 16384;     // 4096
    float* u_sh    = sm + 20480;     // 2 x 128
    float* bvec_sh = sm + 20736;     // 128
    float* dxmn_sh = sm + 20864;     // 128
    float* dxmx_sh = sm + 20992;     // 128

    int tid = threadIdx.x;
    int t = blockIdx.x;
    int o = tid >> 4, l = tid & 15;
    int lh = l >> 3, lj = l & 7;

    // Whf -> registers: thread (o,l) holds W_hf[o][lh*16+i][lj*4..lj*4+3]
    float4 w[16];
    const float4* whf4 = (const float4*)Whf;
    #pragma unroll
    for (int i = 0; i < 16; i++)
        w[i] = whf4[(o * 32 + lh * 16 + i) * 8 + lj];

    size_t tb = (size_t)t * 4096;
    {
        const float4* M4  = (const float4*)(M + tb);
        const float4* DT4 = (const float4*)(DTin + tb);
        const float4* D4  = (const float4*)(Din + tb);
        float4* m4  = (float4*)m_all;
        float4* dt4 = (float4*)dt_all;
        float4* d4  = (float4*)d_all;
        #pragma unroll
        for (int idx = tid; idx < 1024; idx += 512) {
            m4[idx] = M4[idx];
            dt4[idx] = DT4[idx];
            d4[idx] = D4[idx];
        }
    }
    for (int idx = tid; idx < 4096; idx += 512) {
        wb_sh[idx] = g_WB[idx];
        we_sh[idx] = g_WE[idx];
    }
    if (tid < 128) {
        bvec_sh[tid] = g_bvec[tid];
        dxmn_sh[tid] = dxmn_g[tid];
        dxmx_sh[tid] = dxmx_g[tid];
    }
    int uo = tid - 384;   // threads 384..415 own u-output lane uo
    float umn_c[4], umx_c[4], umn_n[4], umx_n[4];
    __syncthreads();

    for (int grp = 0; grp <= 32; grp++) {
        int cur = grp & 1;

        // ---- prefetch UMIN/UMAX for group grp (used at iteration grp+1)
        if (uo >= 0 && uo < 32 && grp < 32) {
            #pragma unroll
            for (int s = 0; s < 4; s++) {
                size_t idx = tb + (size_t)(grp * 4 + s) * 32 + uo;
                umn_n[s] = UMIN[idx];
                umx_n[s] = UMAX[idx];
            }
        }

        // ---- S1: factorized bilinear for samples grp*4 .. grp*4+3
        if (grp < 32) {
            int b0 = grp * 4;
            float4 dtv[4];
            #pragma unroll
            for (int s = 0; s < 4; s++)
                dtv[s] = ((const float4*)(dt_all + (b0 + s) * 32))[lj];
            float acc[4] = {0.f, 0.f, 0.f, 0.f};
            #pragma unroll
            for (int i = 0; i < 16; i++) {
                #pragma unroll
                for (int s = 0; s < 4; s++) {
                    float p = w[i].x * dtv[s].x;
                    p = fmaf(w[i].y, dtv[s].y, p);
                    p = fmaf(w[i].z, dtv[s].z, p);
                    p = fmaf(w[i].w, dtv[s].w, p);
                    acc[s] = fmaf(m_all[(b0 + s) * 32 + lh * 16 + i], p, acc[s]);
                }
            }
            #pragma unroll
            for (int s = 0; s < 4; s++) {
                float a = acc[s];
                a += __shfl_xor_sync(0xffffffffu, a, 1);
                a += __shfl_xor_sync(0xffffffffu, a, 2);
                a += __shfl_xor_sync(0xffffffffu, a, 4);
                a += __shfl_xor_sync(0xffffffffu, a, 8);
                if (l == 0) u_sh[cur * 128 + s * 32 + o] = a;
            }
        }

        // ---- S2: drain group grp-1
        if (grp >= 1) {
            int gb = (grp - 1) * 4;
            int pv = (grp - 1) & 1;
            if (tid < 128) {
                float bu[4] = {0.f, 0.f, 0.f, 0.f};
                float ed[4] = {0.f, 0.f, 0.f, 0.f};
                #pragma unroll
                for (int oo = 0; oo < 32; oo++) {
                    float wbv = wb_sh[oo * 128 + tid];
                    float wev = we_sh[oo * 128 + tid];
                    #pragma unroll
                    for (int s = 0; s < 4; s++) {
                        bu[s] = fmaf(u_sh[pv * 128 + s * 32 + oo], wbv, bu[s]);
                        ed[s] = fmaf(d_all[(gb + s) * 32 + oo], wev, ed[s]);
                    }
                }
                float dn = dxmn_sh[tid], dx = dxmx_sh[tid];
                float bv = bvec_sh[tid];
                #pragma unroll
                for (int s = 0; s < 4; s++) {
                    size_t base128 = ((size_t)t * Bc + (gb + s)) * 128;
                    out[OFF_SDXU + base128 + tid] = relu_f(dn - bu[s]) + relu_f(bu[s] - dx);
                    out[OFF_SDXD + base128 + tid] = relu_f(dn - ed[s]) + relu_f(ed[s] - dx);
                    g_C[base128 + tid] = bu[s] + ed[s] + bv;
                }
            } else if (uo >= 0 && uo < 32) {
                #pragma unroll
                for (int s = 0; s < 4; s++) {
                    float uu = u_sh[pv * 128 + s * 32 + uo];
                    size_t base32 = tb + (size_t)(gb + s) * 32;
                    out[OFF_U + base32 + uo]     = uu;
                    out[OFF_SUMIN + base32 + uo] = relu_f(umn_c[s] - uu);
                    out[OFF_SUMAX + base32 + uo] = relu_f(uu - umx_c[s]);
                }
            }
        }
        // rotate prefetch registers
        if (uo >= 0 && uo < 32) {
            #pragma unroll
            for (int s = 0; s < 4; s++) { umn_c[s] = umn_n[s]; umx_c[s] = umx_n[s]; }
        }
        __syncthreads();
    }
}

// ---------------- kernel 5: sequential rollout -------------------------------
// 128 threads/block; thread j owns column j with ALL 128 W_A weights in
// registers. Double-buffered x -> ONE barrier per step, no reduce round-trip.
__global__ void __launch_bounds__(128) k_seq(
    const float* __restrict__ XMIN, const float* __restrict__ XMAX,
    const float* __restrict__ Cg, float* __restrict__ out)
{
    __shared__ float xbuf[2][128];
    int j = threadIdx.x;
    int b = blockIdx.x;

    float wa[128];
    #pragma unroll
    for (int kk = 0; kk < 128; kk++) wa[kk] = g_WA[kk * 128 + j];

    float xprev = g_x0[b * 128 + j];
    xbuf[0][j] = xprev;

    float c0, c1, mn0, mn1, mx0, mx1;
    {
        size_t i0 = ((size_t)0 * Bc + b) * 128 + j;
        size_t i1 = ((size_t)1 * Bc + b) * 128 + j;
        c0 = Cg[i0]; mn0 = XMIN[i0]; mx0 = XMAX[i0];
        c1 = Cg[i1]; mn1 = XMIN[i1]; mx1 = XMAX[i1];
    }
    __syncthreads();

    for (int t = 0; t < NSTEPSc; t++) {
        int cur = t & 1;
        float a0 = 0.0f, a1 = 0.0f, a2 = 0.0f, a3 = 0.0f;
        const float4* x4 = (const float4*)xbuf[cur];
        #pragma unroll
        for (int kk = 0; kk < 32; kk++) {
            float4 xv = x4[kk];
            a0 = fmaf(xv.x, wa[kk * 4 + 0], a0);
            a1 = fmaf(xv.y, wa[kk * 4 + 1], a1);
            a2 = fmaf(xv.z, wa[kk * 4 + 2], a2);
            a3 = fmaf(xv.w, wa[kk * 4 + 3], a3);
        }
        float xn = (a0 + a1) + (a2 + a3) + c0;
        xbuf[1 - cur][j] = xn;

        // prefetch t+2
        float cn = 0.0f, mnn = 0.0f, mxn = 0.0f;
        if (t + 2 < NSTEPSc) {
            size_t i2 = ((size_t)(t + 2) * Bc + b) * 128 + j;
            cn = Cg[i2]; mnn = XMIN[i2]; mxn = XMAX[i2];
        }

        size_t bi = ((size_t)t * Bc + b) * 128 + j;
        out[OFF_X + bi]     = xn;
        out[OFF_SXMIN + bi] = relu_f(mn0 - xn);
        out[OFF_SXMAX + bi] = relu_f(xn - mx0);
        out[OFF_SDXX + bi]  = xn - xprev;
        xprev = xn;
        c0 = c1; mn0 = mn1; mx0 = mx1;
        c1 = cn; mn1 = mnn; mx1 = mxn;
        __syncthreads();
    }
}

// ---------------- kernel 6: Y = X @ W_C (64 rows/block, weights amortized) ---
__global__ void __launch_bounds__(256) k_post(float* __restrict__ out)
{
    __shared__ float xs[64 * 128];   // 32 KB
    int tid = threadIdx.x;
    size_t row0 = (size_t)blockIdx.x * 64;
    int r0 = tid >> 6, j2 = tid & 63;

    float wc[128];
    #pragma unroll
    for (int kk = 0; kk < 128; kk++) wc[kk] = g_WC[kk * 64 + j2];

    const float4* src = (const float4*)(out + OFF_X + row0 * 128);
    float4* dst4 = (float4*)xs;
    #pragma unroll
    for (int i = 0; i < 8; i++) dst4[tid + i * 256] = src[tid + i * 256];
    __syncthreads();

    #pragma unroll 4
    for (int it = 0; it < 16; it++) {
        int row = it * 4 + r0;
        const float* xr = xs + row * 128;
        float a0 = 0.0f, a1 = 0.0f;
        #pragma unroll
        for (int kk = 0; kk < 64; kk++) {
            a0 = fmaf(xr[kk],      wc[kk],      a0);
            a1 = fmaf(xr[64 + kk], wc[64 + kk], a1);
        }
        out[OFF_Y + (row0 + row) * 64 + j2] = a0 + a1;
    }
}

// ---------------- launch ------------------------------------------------------
extern "C" void kernel_launch(void* const* d_in, const int* in_sizes, int n_in,
                              void* d_out, int out_size)
{
    const float* Ym   = (const float*)d_in[0];
    const float* M    = (const float*)d_in[1];
    const float* DTin = (const float*)d_in[2];
    const float* Din  = (const float*)d_in[3];
    const float* XMIN = (const float*)d_in[4];
    const float* XMAX = (const float*)d_in[5];
    const float* UMIN = (const float*)d_in[6];
    const float* UMAX = (const float*)d_in[7];
    const float* x0c  = (const float*)d_in[8];
    const float* UA   = (const float*)d_in[9];
    const float* sigA = (const float*)d_in[10];
    const float* VA   = (const float*)d_in[11];
    const float* UC   = (const float*)d_in[12];
    const float* sigC = (const float*)d_in[13];
    const float* VC   = (const float*)d_in[14];
    const float* wE   = (const float*)d_in[15];
    const float* sE   = (const float*)d_in[16];
    const float* wB   = (const float*)d_in[17];
    const float* Whf  = (const float*)d_in[18];
    const float* Wih  = (const float*)d_in[19];
    const float* Whh  = (const float*)d_in[20];
    const float* dxmn = (const float*)d_in[21];
    const float* dxmx = (const float*)d_in[22];
    float* out = (float*)d_out;

    static const size_t smem_pre = SM_PRE_FLOATS * sizeof(float);
    cudaFuncSetAttribute(k_pre, cudaFuncAttributeMaxDynamicSharedMemorySize,
                         (int)smem_pre);

    float* Cg = nullptr;
    cudaGetSymbolAddress((void**)&Cg, g_C);

    k_zero<<<1, 32>>>();
    k_setup<<<128, 128>>>(UA, sigA, VA, UC, sigC, VC);
    k_setup2<<<1, 128>>>(x0c, wE, sE, wB, out);
    k_pre<<<NSTEPSc, 512, smem_pre>>>(M, DTin, Din, UMIN, UMAX, Whf, dxmn, dxmx, out);
    k_rnn<<<Bc, 512>>>(Ym, Wih, Whh);
    k_seq<<<Bc, 128>>>(XMIN, XMAX, Cg, out);
    k_post<<<(NSTEPSc * Bc) / 64, 256>>>(out);
}

// round 9
// speedup vs baseline: 2.8636x; 1.1432x over previous
#include <cuda_runtime.h>
#include <math.h>

// Problem dims
#define NXc 128
#define NYc 64
#define NMc 32
#define NDTc 32
#define NUc 32
#define NDc 32
#define NSTEPSc 1024
#define Bc 128
#define TPc 64

// Output offsets (floats) for the flattened 11-tuple
#define OFF_X      ((size_t)0)
#define OFF_Y      ((size_t)16777216)
#define OFF_U      ((size_t)25165824)
#define OFF_SXMIN  ((size_t)29360128)
#define OFF_SXMAX  ((size_t)46137344)
#define OFF_SUMIN  ((size_t)62914560)
#define OFF_SUMAX  ((size_t)67108864)
#define OFF_SDXX   ((size_t)71303168)
#define OFF_SDXU   ((size_t)88080384)
#define OFF_SDXD   ((size_t)104857600)
#define OFF_SPECT  ((size_t)121634816)

// ---------------- module-scope scratch ----------------
__device__ float g_WA[NXc * NXc];
__device__ float g_WA2[NXc * NXc];               // WA @ WA
__device__ float g_WC[NXc * NYc];
__device__ float g_WE[NDc * NXc];
__device__ float g_WB[NUc * NXc];
__device__ float g_bvec[NXc];
__device__ float g_x0[Bc * NXc];
__device__ float g_C[(size_t)NSTEPSc * Bc * NXc];        // 64 MB
__device__ float g_C2[(size_t)(NSTEPSc / 2) * Bc * NXc]; // 32 MB: c_{2p}@WA + c_{2p+1}
__device__ float g_acc[8];

__device__ __forceinline__ float sigmoid_f(float x) { return 1.0f / (1.0f + expf(-x)); }
__device__ __forceinline__ float relu_f(float x) { return fmaxf(x, 0.0f); }
__device__ __forceinline__ float gelu_tanh(float x) {
    float x3 = x * x * x;
    float t = tanhf(0.7978845608028654f * (x + 0.044715f * x3));
    return 0.5f * x * (1.0f + t);
}

// ---------------- kernel 0: zero accumulators --------------------------------
__global__ void k_zero() {
    if (threadIdx.x < 8) g_acc[threadIdx.x] = 0.0f;
}

// ---------------- kernel 1: spectral weights + Gram sums ---------------------
__global__ void __launch_bounds__(128) k_setup(
    const float* __restrict__ UA, const float* __restrict__ sigA, const float* __restrict__ VA,
    const float* __restrict__ UC, const float* __restrict__ sigC, const float* __restrict__ VC)
{
    __shared__ float sA[128], sC[64], rowUA[128], rowUC[64];
    __shared__ float colUA[128], colVA[128], colUC[128], colVC[64];
    __shared__ float red[4];
    int i = blockIdx.x, j = threadIdx.x;

    sA[j] = 0.1f + 0.8f * sigmoid_f(sigA[j]);
    rowUA[j] = UA[i * 128 + j];
    colUA[j] = UA[j * 128 + i];
    colVA[j] = VA[j * 128 + i];
    colUC[j] = UC[j * 128 + i];
    if (j < 64) {
        sC[j] = 0.9f + 0.1f * sigmoid_f(sigC[j]);
        rowUC[j] = UC[i * 128 + j];
        if (i < 64) colVC[j] = VC[j * 64 + i];
    }
    __syncthreads();

    float acc = 0.0f;
    #pragma unroll 8
    for (int k = 0; k < 128; k++) acc = fmaf(rowUA[k] * sA[k], VA[k * 128 + j], acc);
    g_WA[i * 128 + j] = acc;

    if (j < 64) {
        float a = 0.0f;
        #pragma unroll 8
        for (int k = 0; k < 64; k++) a = fmaf(rowUC[k] * sC[k], VC[k * 64 + j], a);
        g_WC[i * 64 + j] = a;
    }

    float gua = 0.0f, gva = 0.0f, guc = 0.0f;
    #pragma unroll 8
    for (int k = 0; k < 128; k++) {
        gua = fmaf(colUA[k], UA[k * 128 + j], gua);
        gva = fmaf(colVA[k], VA[k * 128 + j], gva);
        guc = fmaf(colUC[k], UC[k * 128 + j], guc);
    }
    float p6 = 0.0f, p7 = 0.0f;
    if (i < 64 && j < 64) {
        float g = 0.0f;
        #pragma unroll 8
        for (int k = 0; k < 64; k++) g = fmaf(colVC[k], VC[k * 64 + j], g);
        p6 = g * g;
        float v = VC[i * 64 + j];
        p7 = v * v;
    }
    float part[8];
    part[0] = gua * gua;
    part[1] = rowUA[j] * rowUA[j];
    part[2] = gva * gva;
    { float v = VA[i * 128 + j]; part[3] = v * v; }
    part[4] = guc * guc;
    { float v = UC[i * 128 + j]; part[5] = v * v; }
    part[6] = p6;
    part[7] = p7;

    for (int v = 0; v < 8; v++) {
        float x = part[v];
        #pragma unroll
        for (int o = 16; o; o >>= 1) x += __shfl_xor_sync(0xffffffffu, x, o);
        if ((j & 31) == 0) red[j >> 5] = x;
        __syncthreads();
        if (j == 0) atomicAdd(&g_acc[v], red[0] + red[1] + red[2] + red[3]);
        __syncthreads();
    }
}

// ---------------- kernel 2: W_E, W_B, bvec, SpectErr -------------------------
__global__ void __launch_bounds__(128) k_setup2(
    const float* __restrict__ x0c, const float* __restrict__ wE,
    const float* __restrict__ sE, const float* __restrict__ wB,
    float* __restrict__ out)
{
    __shared__ float xc[128];
    int j = threadIdx.x;
    xc[j] = x0c[j];
    __syncthreads();

    float b = 0.0f;
    #pragma unroll 8
    for (int k = 0; k < 128; k++) b = fmaf(xc[k], g_WA[k * 128 + j], b);
    g_bvec[j] = b;

    float mx = -1e30f;
    for (int i = 0; i < 32; i++) mx = fmaxf(mx, wE[i * 128 + j]);
    float s = 0.0f;
    for (int i = 0; i < 32; i++) s += expf(wE[i * 128 + j] - mx);
    float inv = 1.0f / s;
    for (int i = 0; i < 32; i++) {
        float sm = expf(wE[i * 128 + j] - mx) * inv;
        float sc = 1.0f - 0.95f * sigmoid_f(sE[i * 128 + j]);
        g_WE[i * 128 + j] = sc * sm;
    }
    for (int idx = j; idx < NUc * NXc; idx += 128) g_WB[idx] = relu_f(wB[idx]);

    float errA = (g_acc[0] - 2.0f * g_acc[1] + 128.0f) * (1.0f / 16384.0f)
               + (g_acc[2] - 2.0f * g_acc[3] + 128.0f) * (1.0f / 16384.0f);
    float errC = (g_acc[4] - 2.0f * g_acc[5] + 128.0f) * (1.0f / 16384.0f)
               + (g_acc[6] - 2.0f * g_acc[7] + 64.0f) * (1.0f / 4096.0f);
    float sp = errA + errC;
    for (int idx = j; idx < NSTEPSc; idx += 128) out[OFF_SPECT + idx] = sp;
}

// ---------------- kernel: WA2 = WA @ WA --------------------------------------
__global__ void __launch_bounds__(128) k_wa2() {
    __shared__ float rowA[128];
    int i = blockIdx.x, j = threadIdx.x;
    rowA[j] = g_WA[i * 128 + j];
    __syncthreads();
    float acc = 0.0f;
    #pragma unroll 8
    for (int k = 0; k < 128; k++) acc = fmaf(rowA[k], g_WA[k * 128 + j], acc);
    g_WA2[i * 128 + j] = acc;
}

// ---------------- kernel 3: RNN warmup (proven version) ----------------------
__global__ void __launch_bounds__(512) k_rnn(
    const float* __restrict__ Ym, const float* __restrict__ Wih,
    const float* __restrict__ Whh)
{
    __shared__ float h_sh[128];
    __shared__ float ym_sh[2][64];
    __shared__ float p_sh[3 * 128];
    int tid = threadIdx.x;
    int b = blockIdx.x;
    int j = tid & 127, h = tid >> 7;

    float whh_r[32];
    #pragma unroll
    for (int kk = 0; kk < 32; kk++) whh_r[kk] = Whh[(h * 32 + kk) * 128 + j];
    float wih_r[16];
    #pragma unroll
    for (int kk = 0; kk < 16; kk++) wih_r[kk] = Wih[(h * 16 + kk) * 128 + j];

    if (tid < 128) h_sh[tid] = 0.0f;
    if (tid >= 448) ym_sh[0][tid - 448] = Ym[(size_t)b * 64 + (tid - 448)];
    __syncthreads();

    for (int t = 0; t < TPc; t++) {
        const float* yc = ym_sh[t & 1];
        float acc = 0.0f;
        #pragma unroll
        for (int kk = 0; kk < 16; kk++)
            acc = fmaf(yc[h * 16 + kk], wih_r[kk], acc);
        #pragma unroll
        for (int kk = 0; kk < 32; kk++)
            acc = fmaf(h_sh[h * 32 + kk], whh_r[kk], acc);

        if (tid >= 448 && t + 1 < TPc)
            ym_sh[(t + 1) & 1][tid - 448] = Ym[((size_t)(t + 1) * Bc + b) * 64 + (tid - 448)];

        if (h) p_sh[(h - 1) * 128 + j] = acc;
        __syncthreads();
        if (h == 0)
            h_sh[j] = gelu_tanh(acc + p_sh[j] + p_sh[128 + j] + p_sh[256 + j]);
        __syncthreads();
    }
    if (tid < 128) g_x0[b * 128 + tid] = h_sh[tid];
}

// ---------------- kernel 4: precompute, 4-sample batched ---------------------
#define SM_PRE_FLOATS (4096*3 + 4096*2 + 256 + 128*3)
__global__ void __launch_bounds__(512) k_pre(
    const float* __restrict__ M, const float* __restrict__ DTin,
    const float* __restrict__ Din, const float* __restrict__ UMIN,
    const float* __restrict__ UMAX, const float* __restrict__ Whf,
    const float* __restrict__ dxmn_g, const float* __restrict__ dxmx_g,
    float* __restrict__ out)
{
    extern __shared__ float sm[];
    float* m_all   = sm;             // 4096
    float* dt_all  = sm + 4096;      // 4096
    float* d_all   = sm + 8192;      // 4096
    float* wb_sh   = sm + 12288;     // 4096
    float* we_sh   = sm + 16384;     // 4096
    float* u_sh    = sm + 20480;     // 2 x 128
    float* bvec_sh = sm + 20736;     // 128
    float* dxmn_sh = sm + 20864;     // 128
    float* dxmx_sh = sm + 20992;     // 128

    int tid = threadIdx.x;
    int t = blockIdx.x;
    int o = tid >> 4, l = tid & 15;
    int lh = l >> 3, lj = l & 7;

    float4 w[16];
    const float4* whf4 = (const float4*)Whf;
    #pragma unroll
    for (int i = 0; i < 16; i++)
        w[i] = whf4[(o * 32 + lh * 16 + i) * 8 + lj];

    size_t tb = (size_t)t * 4096;
    {
        const float4* M4  = (const float4*)(M + tb);
        const float4* DT4 = (const float4*)(DTin + tb);
        const float4* D4  = (const float4*)(Din + tb);
        float4* m4  = (float4*)m_all;
        float4* dt4 = (float4*)dt_all;
        float4* d4  = (float4*)d_all;
        #pragma unroll
        for (int idx = tid; idx < 1024; idx += 512) {
            m4[idx] = M4[idx];
            dt4[idx] = DT4[idx];
            d4[idx] = D4[idx];
        }
    }
    for (int idx = tid; idx < 4096; idx += 512) {
        wb_sh[idx] = g_WB[idx];
        we_sh[idx] = g_WE[idx];
    }
    if (tid < 128) {
        bvec_sh[tid] = g_bvec[tid];
        dxmn_sh[tid] = dxmn_g[tid];
        dxmx_sh[tid] = dxmx_g[tid];
    }
    int uo = tid - 384;
    float umn_c[4], umx_c[4], umn_n[4], umx_n[4];
    __syncthreads();

    for (int grp = 0; grp <= 32; grp++) {
        int cur = grp & 1;

        if (uo >= 0 && uo < 32 && grp < 32) {
            #pragma unroll
            for (int s = 0; s < 4; s++) {
                size_t idx = tb + (size_t)(grp * 4 + s) * 32 + uo;
                umn_n[s] = UMIN[idx];
                umx_n[s] = UMAX[idx];
            }
        }

        // ---- S1: factorized bilinear for samples grp*4 .. grp*4+3
        if (grp < 32) {
            int b0 = grp * 4;
            float4 dtv[4];
            #pragma unroll
            for (int s = 0; s < 4; s++)
                dtv[s] = ((const float4*)(dt_all + (b0 + s) * 32))[lj];
            float acc[4] = {0.f, 0.f, 0.f, 0.f};
            #pragma unroll
            for (int i4 = 0; i4 < 4; i4++) {
                float4 mv[4];
                #pragma unroll
                for (int s = 0; s < 4; s++)
                    mv[s] = ((const float4*)(m_all + (b0 + s) * 32 + lh * 16))[i4];
                #pragma unroll
                for (int s = 0; s < 4; s++) {
                    int i = i4 * 4;
                    float p0 = w[i].x * dtv[s].x;
                    p0 = fmaf(w[i].y, dtv[s].y, p0);
                    p0 = fmaf(w[i].z, dtv[s].z, p0);
                    p0 = fmaf(w[i].w, dtv[s].w, p0);
                    acc[s] = fmaf(mv[s].x, p0, acc[s]);
                    float p1 = w[i + 1].x * dtv[s].x;
                    p1 = fmaf(w[i + 1].y, dtv[s].y, p1);
                    p1 = fmaf(w[i + 1].z, dtv[s].z, p1);
                    p1 = fmaf(w[i + 1].w, dtv[s].w, p1);
                    acc[s] = fmaf(mv[s].y, p1, acc[s]);
                    float p2 = w[i + 2].x * dtv[s].x;
                    p2 = fmaf(w[i + 2].y, dtv[s].y, p2);
                    p2 = fmaf(w[i + 2].z, dtv[s].z, p2);
                    p2 = fmaf(w[i + 2].w, dtv[s].w, p2);
                    acc[s] = fmaf(mv[s].z, p2, acc[s]);
                    float p3 = w[i + 3].x * dtv[s].x;
                    p3 = fmaf(w[i + 3].y, dtv[s].y, p3);
                    p3 = fmaf(w[i + 3].z, dtv[s].z, p3);
                    p3 = fmaf(w[i + 3].w, dtv[s].w, p3);
                    acc[s] = fmaf(mv[s].w, p3, acc[s]);
                }
            }
            #pragma unroll
            for (int s = 0; s < 4; s++) {
                float a = acc[s];
                a += __shfl_xor_sync(0xffffffffu, a, 1);
                a += __shfl_xor_sync(0xffffffffu, a, 2);
                a += __shfl_xor_sync(0xffffffffu, a, 4);
                a += __shfl_xor_sync(0xffffffffu, a, 8);
                if (l == 0) u_sh[cur * 128 + s * 32 + o] = a;
            }
        }

        // ---- S2: drain group grp-1
        if (grp >= 1) {
            int gb = (grp - 1) * 4;
            int pv = (grp - 1) & 1;
            if (tid < 128) {
                float bu[4] = {0.f, 0.f, 0.f, 0.f};
                float ed[4] = {0.f, 0.f, 0.f, 0.f};
                #pragma unroll
                for (int oo = 0; oo < 32; oo++) {
                    float wbv = wb_sh[oo * 128 + tid];
                    float wev = we_sh[oo * 128 + tid];
                    #pragma unroll
                    for (int s = 0; s < 4; s++) {
                        bu[s] = fmaf(u_sh[pv * 128 + s * 32 + oo], wbv, bu[s]);
                        ed[s] = fmaf(d_all[(gb + s) * 32 + oo], wev, ed[s]);
                    }
                }
                float dn = dxmn_sh[tid], dx = dxmx_sh[tid];
                float bv = bvec_sh[tid];
                #pragma unroll
                for (int s = 0; s < 4; s++) {
                    size_t base128 = ((size_t)t * Bc + (gb + s)) * 128;
                    out[OFF_SDXU + base128 + tid] = relu_f(dn - bu[s]) + relu_f(bu[s] - dx);
                    out[OFF_SDXD + base128 + tid] = relu_f(dn - ed[s]) + relu_f(ed[s] - dx);
                    g_C[base128 + tid] = bu[s] + ed[s] + bv;
                }
            } else if (uo >= 0 && uo < 32) {
                #pragma unroll
                for (int s = 0; s < 4; s++) {
                    float uu = u_sh[pv * 128 + s * 32 + uo];
                    size_t base32 = tb + (size_t)(gb + s) * 32;
                    out[OFF_U + base32 + uo]     = uu;
                    out[OFF_SUMIN + base32 + uo] = relu_f(umn_c[s] - uu);
                    out[OFF_SUMAX + base32 + uo] = relu_f(uu - umx_c[s]);
                }
            }
        }
        if (uo >= 0 && uo < 32) {
            #pragma unroll
            for (int s = 0; s < 4; s++) { umn_c[s] = umn_n[s]; umx_c[s] = umx_n[s]; }
        }
        __syncthreads();
    }
}

// ---------------- kernel: C2_p = c_{2p} @ WA + c_{2p+1} ----------------------
// k_post-style streaming: 64 rows/block, WA column in 128 regs, no per-row sync.
__global__ void __launch_bounds__(128) k_c2(const float* __restrict__ Cg)
{
    __shared__ float cs[64 * 128];   // 32 KB
    int j = threadIdx.x;
    int p = blockIdx.x >> 1;
    int boff = (blockIdx.x & 1) * 64;

    float wa[128];
    #pragma unroll
    for (int kk = 0; kk < 128; kk++) wa[kk] = g_WA[kk * 128 + j];

    const float4* src = (const float4*)(Cg + ((size_t)(2 * p) * Bc + boff) * 128);
    float4* dst = (float4*)cs;
    #pragma unroll
    for (int i = 0; i < 16; i++) dst[j + i * 128] = src[j + i * 128];
    __syncthreads();

    const float* codd = Cg + ((size_t)(2 * p + 1) * Bc + boff) * 128;
    float* o = g_C2 + ((size_t)p * Bc + boff) * 128;
    #pragma unroll 4
    for (int r = 0; r < 64; r++) {
        float add = codd[r * 128 + j];
        const float* cr = cs + r * 128;
        float a0 = 0.0f, a1 = 0.0f;
        #pragma unroll
        for (int kk = 0; kk < 64; kk++) {
            a0 = fmaf(cr[kk],      wa[kk],      a0);
            a1 = fmaf(cr[64 + kk], wa[64 + kk], a1);
        }
        o[r * 128 + j] = a0 + a1 + add;
    }
}

// ---------------- kernel 5: sequential rollout, 2 steps per barrier ----------
// x_{t+1} = x_t@WA + c_t ; x_{t+2} = x_t@WA2 + C2 — both from the SAME x_t.
// 256 threads: pair (j, h) adjacent in-warp; h-half k-split; shfl(1) reduce.
__global__ void __launch_bounds__(256) k_seq(
    const float* __restrict__ XMIN, const float* __restrict__ XMAX,
    const float* __restrict__ Cg, float* __restrict__ out)
{
    __shared__ float xbuf[2][128];
    int tid = threadIdx.x;
    int b = blockIdx.x;
    int j = tid >> 1, h = tid & 1;

    float wa[64], wa2[64];
    #pragma unroll
    for (int kk = 0; kk < 64; kk++) {
        wa[kk]  = g_WA [(h * 64 + kk) * 128 + j];
        wa2[kk] = g_WA2[(h * 64 + kk) * 128 + j];
    }

    float xprev = g_x0[b * 128 + j];
    if (h == 0) xbuf[0][j] = xprev;

    // prefetch ring depth 2 (phases 0, 1)
    float cA[2], mnr[2], mxr[2];
    #pragma unroll
    for (int pp = 0; pp < 2; pp++) {
        int ts = 2 * pp + h;
        size_t ib = ((size_t)ts * Bc + b) * 128 + j;
        mnr[pp] = XMIN[ib];
        mxr[pp] = XMAX[ib];
        cA[pp] = h ? g_C2[((size_t)pp * Bc + b) * 128 + j] : Cg[ib];
    }
    __syncthreads();

    for (int p = 0; p < NSTEPSc / 2; p++) {
        int cur = p & 1;
        const float4* x4 = ((const float4*)xbuf[cur]) + h * 16;
        float p1a = 0.f, p1b = 0.f, p2a = 0.f, p2b = 0.f;
        #pragma unroll
        for (int kk = 0; kk < 16; kk++) {
            float4 xv = x4[kk];
            p1a = fmaf(xv.x, wa[kk * 4 + 0], p1a);
            p1b = fmaf(xv.y, wa[kk * 4 + 1], p1b);
            p1a = fmaf(xv.z, wa[kk * 4 + 2], p1a);
            p1b = fmaf(xv.w, wa[kk * 4 + 3], p1b);
            p2a = fmaf(xv.x, wa2[kk * 4 + 0], p2a);
            p2b = fmaf(xv.y, wa2[kk * 4 + 1], p2b);
            p2a = fmaf(xv.z, wa2[kk * 4 + 2], p2a);
            p2b = fmaf(xv.w, wa2[kk * 4 + 3], p2b);
        }
        float y1p = p1a + p1b, y2p = p2a + p2b;
        float y1o = __shfl_xor_sync(0xffffffffu, y1p, 1);
        float y2o = __shfl_xor_sync(0xffffffffu, y2p, 1);
        float cmine = cA[cur];
        float coth  = __shfl_xor_sync(0xffffffffu, cmine, 1);
        float ct = h ? coth : cmine;
        float c2 = h ? cmine : coth;
        float y1 = y1p + y1o + ct;
        float y2 = y2p + y2o + c2;

        int ts = 2 * p + h;
        size_t bi = ((size_t)ts * Bc + b) * 128 + j;
        float yv = h ? y2 : y1;
        out[OFF_X + bi]     = yv;
        out[OFF_SXMIN + bi] = relu_f(mnr[cur] - yv);
        out[OFF_SXMAX + bi] = relu_f(yv - mxr[cur]);
        out[OFF_SDXX + bi]  = h ? (y2 - y1) : (y1 - xprev);
        xprev = y2;
        if (h == 0) xbuf[1 - cur][j] = y2;

        // refill ring for phase p+2
        if (p + 2 < NSTEPSc / 2) {
            int tn = 2 * (p + 2) + h;
            size_t ib = ((size_t)tn * Bc + b) * 128 + j;
            mnr[cur] = XMIN[ib];
            mxr[cur] = XMAX[ib];
            cA[cur] = h ? g_C2[((size_t)(p + 2) * Bc + b) * 128 + j] : Cg[ib];
        }
        __syncthreads();
    }
}

// ---------------- kernel 6: Y = X @ W_C (64 rows/block, weights amortized) ---
__global__ void __launch_bounds__(256) k_post(float* __restrict__ out)
{
    __shared__ float xs[64 * 128];   // 32 KB
    int tid = threadIdx.x;
    size_t row0 = (size_t)blockIdx.x * 64;
    int r0 = tid >> 6, j2 = tid & 63;

    float wc[128];
    #pragma unroll
    for (int kk = 0; kk < 128; kk++) wc[kk] = g_WC[kk * 64 + j2];

    const float4* src = (const float4*)(out + OFF_X + row0 * 128);
    float4* dst4 = (float4*)xs;
    #pragma unroll
    for (int i = 0; i < 8; i++) dst4[tid + i * 256] = src[tid + i * 256];
    __syncthreads();

    #pragma unroll 4
    for (int it = 0; it < 16; it++) {
        int row = it * 4 + r0;
        const float* xr = xs + row * 128;
        float a0 = 0.0f, a1 = 0.0f;
        #pragma unroll
        for (int kk = 0; kk < 64; kk++) {
            a0 = fmaf(xr[kk],      wc[kk],      a0);
            a1 = fmaf(xr[64 + kk], wc[64 + kk], a1);
        }
        out[OFF_Y + (row0 + row) * 64 + j2] = a0 + a1;
    }
}

// ---------------- launch ------------------------------------------------------
extern "C" void kernel_launch(void* const* d_in, const int* in_sizes, int n_in,
                              void* d_out, int out_size)
{
    const float* Ym   = (const float*)d_in[0];
    const float* M    = (const float*)d_in[1];
    const float* DTin = (const float*)d_in[2];
    const float* Din  = (const float*)d_in[3];
    const float* XMIN = (const float*)d_in[4];
    const float* XMAX = (const float*)d_in[5];
    const float* UMIN = (const float*)d_in[6];
    const float* UMAX = (const float*)d_in[7];
    const float* x0c  = (const float*)d_in[8];
    const float* UA   = (const float*)d_in[9];
    const float* sigA = (const float*)d_in[10];
    const float* VA   = (const float*)d_in[11];
    const float* UC   = (const float*)d_in[12];
    const float* sigC = (const float*)d_in[13];
    const float* VC   = (const float*)d_in[14];
    const float* wE   = (const float*)d_in[15];
    const float* sE   = (const float*)d_in[16];
    const float* wB   = (const float*)d_in[17];
    const float* Whf  = (const float*)d_in[18];
    const float* Wih  = (const float*)d_in[19];
    const float* Whh  = (const float*)d_in[20];
    const float* dxmn = (const float*)d_in[21];
    const float* dxmx = (const float*)d_in[22];
    float* out = (float*)d_out;

    static const size_t smem_pre = SM_PRE_FLOATS * sizeof(float);
    cudaFuncSetAttribute(k_pre, cudaFuncAttributeMaxDynamicSharedMemorySize,
                         (int)smem_pre);

    float* Cg = nullptr;
    cudaGetSymbolAddress((void**)&Cg, g_C);

    k_zero<<<1, 32>>>();
    k_setup<<<128, 128>>>(UA, sigA, VA, UC, sigC, VC);
    k_setup2<<<1, 128>>>(x0c, wE, sE, wB, out);
    k_pre<<<NSTEPSc, 512, smem_pre>>>(M, DTin, Din, UMIN, UMAX, Whf, dxmn, dxmx, out);
    k_wa2<<<128, 128>>>();
    k_rnn<<<Bc, 512>>>(Ym, Wih, Whh);
    k_c2<<<NSTEPSc, 128>>>(Cg);   // 1024 blocks: 2 blocks per phase p
    k_seq<<<Bc, 256>>>(XMIN, XMAX, Cg, out);
    k_post<<<(NSTEPSc * Bc) / 64, 256>>>(out);
}

// round 10
// speedup vs baseline: 2.9587x; 1.0332x over previous
#include <cuda_runtime.h>
#include <math.h>

// Problem dims
#define NXc 128
#define NYc 64
#define NMc 32
#define NDTc 32
#define NUc 32
#define NDc 32
#define NSTEPSc 1024
#define Bc 128
#define TPc 64

// Output offsets (floats) for the flattened 11-tuple
#define OFF_X      ((size_t)0)
#define OFF_Y      ((size_t)16777216)
#define OFF_U      ((size_t)25165824)
#define OFF_SXMIN  ((size_t)29360128)
#define OFF_SXMAX  ((size_t)46137344)
#define OFF_SUMIN  ((size_t)62914560)
#define OFF_SUMAX  ((size_t)67108864)
#define OFF_SDXX   ((size_t)71303168)
#define OFF_SDXU   ((size_t)88080384)
#define OFF_SDXD   ((size_t)104857600)
#define OFF_SPECT  ((size_t)121634816)

// ---------------- module-scope scratch ----------------
__device__ float g_WA[NXc * NXc];
__device__ float g_WA2[NXc * NXc];               // WA @ WA
__device__ float g_WC[NXc * NYc];
__device__ float g_WE[NDc * NXc];
__device__ float g_WB[NUc * NXc];
__device__ float g_bvec[NXc];
__device__ float g_x0[Bc * NXc];
__device__ float g_C[(size_t)NSTEPSc * Bc * NXc];        // 64 MB
__device__ float g_C2[(size_t)(NSTEPSc / 2) * Bc * NXc]; // 32 MB: c_{2p}@WA + c_{2p+1}
__device__ float g_acc[8];

__device__ __forceinline__ float sigmoid_f(float x) { return 1.0f / (1.0f + expf(-x)); }
__device__ __forceinline__ float relu_f(float x) { return fmaxf(x, 0.0f); }
__device__ __forceinline__ float gelu_tanh(float x) {
    float x3 = x * x * x;
    float t = tanhf(0.7978845608028654f * (x + 0.044715f * x3));
    return 0.5f * x * (1.0f + t);
}

// ---------------- kernel 0: zero accumulators --------------------------------
__global__ void k_zero() {
    if (threadIdx.x < 8) g_acc[threadIdx.x] = 0.0f;
}

// ---------------- kernel 1: spectral weights + Gram sums ---------------------
__global__ void __launch_bounds__(128) k_setup(
    const float* __restrict__ UA, const float* __restrict__ sigA, const float* __restrict__ VA,
    const float* __restrict__ UC, const float* __restrict__ sigC, const float* __restrict__ VC)
{
    __shared__ float sA[128], sC[64], rowUA[128], rowUC[64];
    __shared__ float colUA[128], colVA[128], colUC[128], colVC[64];
    __shared__ float red[4];
    int i = blockIdx.x, j = threadIdx.x;

    sA[j] = 0.1f + 0.8f * sigmoid_f(sigA[j]);
    rowUA[j] = UA[i * 128 + j];
    colUA[j] = UA[j * 128 + i];
    colVA[j] = VA[j * 128 + i];
    colUC[j] = UC[j * 128 + i];
    if (j < 64) {
        sC[j] = 0.9f + 0.1f * sigmoid_f(sigC[j]);
        rowUC[j] = UC[i * 128 + j];
        if (i < 64) colVC[j] = VC[j * 64 + i];
    }
    __syncthreads();

    float acc = 0.0f;
    #pragma unroll 8
    for (int k = 0; k < 128; k++) acc = fmaf(rowUA[k] * sA[k], VA[k * 128 + j], acc);
    g_WA[i * 128 + j] = acc;

    if (j < 64) {
        float a = 0.0f;
        #pragma unroll 8
        for (int k = 0; k < 64; k++) a = fmaf(rowUC[k] * sC[k], VC[k * 64 + j], a);
        g_WC[i * 64 + j] = a;
    }

    float gua = 0.0f, gva = 0.0f, guc = 0.0f;
    #pragma unroll 8
    for (int k = 0; k < 128; k++) {
        gua = fmaf(colUA[k], UA[k * 128 + j], gua);
        gva = fmaf(colVA[k], VA[k * 128 + j], gva);
        guc = fmaf(colUC[k], UC[k * 128 + j], guc);
    }
    float p6 = 0.0f, p7 = 0.0f;
    if (i < 64 && j < 64) {
        float g = 0.0f;
        #pragma unroll 8
        for (int k = 0; k < 64; k++) g = fmaf(colVC[k], VC[k * 64 + j], g);
        p6 = g * g;
        float v = VC[i * 64 + j];
        p7 = v * v;
    }
    float part[8];
    part[0] = gua * gua;
    part[1] = rowUA[j] * rowUA[j];
    part[2] = gva * gva;
    { float v = VA[i * 128 + j]; part[3] = v * v; }
    part[4] = guc * guc;
    { float v = UC[i * 128 + j]; part[5] = v * v; }
    part[6] = p6;
    part[7] = p7;

    for (int v = 0; v < 8; v++) {
        float x = part[v];
        #pragma unroll
        for (int o = 16; o; o >>= 1) x += __shfl_xor_sync(0xffffffffu, x, o);
        if ((j & 31) == 0) red[j >> 5] = x;
        __syncthreads();
        if (j == 0) atomicAdd(&g_acc[v], red[0] + red[1] + red[2] + red[3]);
        __syncthreads();
    }
}

// ---------------- kernel 2: W_E, W_B, bvec, SpectErr -------------------------
__global__ void __launch_bounds__(128) k_setup2(
    const float* __restrict__ x0c, const float* __restrict__ wE,
    const float* __restrict__ sE, const float* __restrict__ wB,
    float* __restrict__ out)
{
    __shared__ float xc[128];
    int j = threadIdx.x;
    xc[j] = x0c[j];
    __syncthreads();

    float b = 0.0f;
    #pragma unroll 8
    for (int k = 0; k < 128; k++) b = fmaf(xc[k], g_WA[k * 128 + j], b);
    g_bvec[j] = b;

    float mx = -1e30f;
    for (int i = 0; i < 32; i++) mx = fmaxf(mx, wE[i * 128 + j]);
    float s = 0.0f;
    for (int i = 0; i < 32; i++) s += expf(wE[i * 128 + j] - mx);
    float inv = 1.0f / s;
    for (int i = 0; i < 32; i++) {
        float sm = expf(wE[i * 128 + j] - mx) * inv;
        float sc = 1.0f - 0.95f * sigmoid_f(sE[i * 128 + j]);
        g_WE[i * 128 + j] = sc * sm;
    }
    for (int idx = j; idx < NUc * NXc; idx += 128) g_WB[idx] = relu_f(wB[idx]);

    float errA = (g_acc[0] - 2.0f * g_acc[1] + 128.0f) * (1.0f / 16384.0f)
               + (g_acc[2] - 2.0f * g_acc[3] + 128.0f) * (1.0f / 16384.0f);
    float errC = (g_acc[4] - 2.0f * g_acc[5] + 128.0f) * (1.0f / 16384.0f)
               + (g_acc[6] - 2.0f * g_acc[7] + 64.0f) * (1.0f / 4096.0f);
    float sp = errA + errC;
    for (int idx = j; idx < NSTEPSc; idx += 128) out[OFF_SPECT + idx] = sp;
}

// ---------------- kernel: WA2 = WA @ WA --------------------------------------
__global__ void __launch_bounds__(128) k_wa2() {
    __shared__ float rowA[128];
    int i = blockIdx.x, j = threadIdx.x;
    rowA[j] = g_WA[i * 128 + j];
    __syncthreads();
    float acc = 0.0f;
    #pragma unroll 8
    for (int k = 0; k < 128; k++) acc = fmaf(rowA[k], g_WA[k * 128 + j], acc);
    g_WA2[i * 128 + j] = acc;
}

// ---------------- kernel 3: RNN warmup (proven version) ----------------------
__global__ void __launch_bounds__(512) k_rnn(
    const float* __restrict__ Ym, const float* __restrict__ Wih,
    const float* __restrict__ Whh)
{
    __shared__ float h_sh[128];
    __shared__ float ym_sh[2][64];
    __shared__ float p_sh[3 * 128];
    int tid = threadIdx.x;
    int b = blockIdx.x;
    int j = tid & 127, h = tid >> 7;

    float whh_r[32];
    #pragma unroll
    for (int kk = 0; kk < 32; kk++) whh_r[kk] = Whh[(h * 32 + kk) * 128 + j];
    float wih_r[16];
    #pragma unroll
    for (int kk = 0; kk < 16; kk++) wih_r[kk] = Wih[(h * 16 + kk) * 128 + j];

    if (tid < 128) h_sh[tid] = 0.0f;
    if (tid >= 448) ym_sh[0][tid - 448] = Ym[(size_t)b * 64 + (tid - 448)];
    __syncthreads();

    for (int t = 0; t < TPc; t++) {
        const float* yc = ym_sh[t & 1];
        float acc = 0.0f;
        #pragma unroll
        for (int kk = 0; kk < 16; kk++)
            acc = fmaf(yc[h * 16 + kk], wih_r[kk], acc);
        #pragma unroll
        for (int kk = 0; kk < 32; kk++)
            acc = fmaf(h_sh[h * 32 + kk], whh_r[kk], acc);

        if (tid >= 448 && t + 1 < TPc)
            ym_sh[(t + 1) & 1][tid - 448] = Ym[((size_t)(t + 1) * Bc + b) * 64 + (tid - 448)];

        if (h) p_sh[(h - 1) * 128 + j] = acc;
        __syncthreads();
        if (h == 0)
            h_sh[j] = gelu_tanh(acc + p_sh[j] + p_sh[128 + j] + p_sh[256 + j]);
        __syncthreads();
    }
    if (tid < 128) g_x0[b * 128 + tid] = h_sh[tid];
}

// ---------------- kernel 4: precompute, 4-sample batched (R8/R9 proven) ------
#define SM_PRE_FLOATS (4096*3 + 4096*2 + 256 + 128*3)
__global__ void __launch_bounds__(512) k_pre(
    const float* __restrict__ M, const float* __restrict__ DTin,
    const float* __restrict__ Din, const float* __restrict__ UMIN,
    const float* __restrict__ UMAX, const float* __restrict__ Whf,
    const float* __restrict__ dxmn_g, const float* __restrict__ dxmx_g,
    float* __restrict__ out)
{
    extern __shared__ float sm[];
    float* m_all   = sm;             // 4096
    float* dt_all  = sm + 4096;      // 4096
    float* d_all   = sm + 8192;      // 4096
    float* wb_sh   = sm + 12288;     // 4096
    float* we_sh   = sm + 16384;     // 4096
    float* u_sh    = sm + 20480;     // 2 x 128
    float* bvec_sh = sm + 20736;     // 128
    float* dxmn_sh = sm + 20864;     // 128
    float* dxmx_sh = sm + 20992;     // 128

    int tid = threadIdx.x;
    int t = blockIdx.x;
    int o = tid >> 4, l = tid & 15;
    int lh = l >> 3, lj = l & 7;

    float4 w[16];
    const float4* whf4 = (const float4*)Whf;
    #pragma unroll
    for (int i = 0; i < 16; i++)
        w[i] = whf4[(o * 32 + lh * 16 + i) * 8 + lj];

    size_t tb = (size_t)t * 4096;
    {
        const float4* M4  = (const float4*)(M + tb);
        const float4* DT4 = (const float4*)(DTin + tb);
        const float4* D4  = (const float4*)(Din + tb);
        float4* m4  = (float4*)m_all;
        float4* dt4 = (float4*)dt_all;
        float4* d4  = (float4*)d_all;
        #pragma unroll
        for (int idx = tid; idx < 1024; idx += 512) {
            m4[idx] = M4[idx];
            dt4[idx] = DT4[idx];
            d4[idx] = D4[idx];
        }
    }
    for (int idx = tid; idx < 4096; idx += 512) {
        wb_sh[idx] = g_WB[idx];
        we_sh[idx] = g_WE[idx];
    }
    if (tid < 128) {
        bvec_sh[tid] = g_bvec[tid];
        dxmn_sh[tid] = dxmn_g[tid];
        dxmx_sh[tid] = dxmx_g[tid];
    }
    int uo = tid - 384;
    float umn_c[4], umx_c[4], umn_n[4], umx_n[4];
    __syncthreads();

    for (int grp = 0; grp <= 32; grp++) {
        int cur = grp & 1;

        if (uo >= 0 && uo < 32 && grp < 32) {
            #pragma unroll
            for (int s = 0; s < 4; s++) {
                size_t idx = tb + (size_t)(grp * 4 + s) * 32 + uo;
                umn_n[s] = UMIN[idx];
                umx_n[s] = UMAX[idx];
            }
        }

        // ---- S1: factorized bilinear for samples grp*4 .. grp*4+3
        if (grp < 32) {
            int b0 = grp * 4;
            float4 dtv[4];
            #pragma unroll
            for (int s = 0; s < 4; s++)
                dtv[s] = ((const float4*)(dt_all + (b0 + s) * 32))[lj];
            float acc[4] = {0.f, 0.f, 0.f, 0.f};
            #pragma unroll
            for (int i4 = 0; i4 < 4; i4++) {
                float4 mv[4];
                #pragma unroll
                for (int s = 0; s < 4; s++)
                    mv[s] = ((const float4*)(m_all + (b0 + s) * 32 + lh * 16))[i4];
                #pragma unroll
                for (int s = 0; s < 4; s++) {
                    int i = i4 * 4;
                    float p0 = w[i].x * dtv[s].x;
                    p0 = fmaf(w[i].y, dtv[s].y, p0);
                    p0 = fmaf(w[i].z, dtv[s].z, p0);
                    p0 = fmaf(w[i].w, dtv[s].w, p0);
                    acc[s] = fmaf(mv[s].x, p0, acc[s]);
                    float p1 = w[i + 1].x * dtv[s].x;
                    p1 = fmaf(w[i + 1].y, dtv[s].y, p1);
                    p1 = fmaf(w[i + 1].z, dtv[s].z, p1);
                    p1 = fmaf(w[i + 1].w, dtv[s].w, p1);
                    acc[s] = fmaf(mv[s].y, p1, acc[s]);
                    float p2 = w[i + 2].x * dtv[s].x;
                    p2 = fmaf(w[i + 2].y, dtv[s].y, p2);
                    p2 = fmaf(w[i + 2].z, dtv[s].z, p2);
                    p2 = fmaf(w[i + 2].w, dtv[s].w, p2);
                    acc[s] = fmaf(mv[s].z, p2, acc[s]);
                    float p3 = w[i + 3].x * dtv[s].x;
                    p3 = fmaf(w[i + 3].y, dtv[s].y, p3);
                    p3 = fmaf(w[i + 3].z, dtv[s].z, p3);
                    p3 = fmaf(w[i + 3].w, dtv[s].w, p3);
                    acc[s] = fmaf(mv[s].w, p3, acc[s]);
                }
            }
            #pragma unroll
            for (int s = 0; s < 4; s++) {
                float a = acc[s];
                a += __shfl_xor_sync(0xffffffffu, a, 1);
                a += __shfl_xor_sync(0xffffffffu, a, 2);
                a += __shfl_xor_sync(0xffffffffu, a, 4);
                a += __shfl_xor_sync(0xffffffffu, a, 8);
                if (l == 0) u_sh[cur * 128 + s * 32 + o] = a;
            }
        }

        // ---- S2: drain group grp-1
        if (grp >= 1) {
            int gb = (grp - 1) * 4;
            int pv = (grp - 1) & 1;
            if (tid < 128) {
                float bu[4] = {0.f, 0.f, 0.f, 0.f};
                float ed[4] = {0.f, 0.f, 0.f, 0.f};
                #pragma unroll
                for (int oo = 0; oo < 32; oo++) {
                    float wbv = wb_sh[oo * 128 + tid];
                    float wev = we_sh[oo * 128 + tid];
                    #pragma unroll
                    for (int s = 0; s < 4; s++) {
                        bu[s] = fmaf(u_sh[pv * 128 + s * 32 + oo], wbv, bu[s]);
                        ed[s] = fmaf(d_all[(gb + s) * 32 + oo], wev, ed[s]);
                    }
                }
                float dn = dxmn_sh[tid], dx = dxmx_sh[tid];
                float bv = bvec_sh[tid];
                #pragma unroll
                for (int s = 0; s < 4; s++) {
                    size_t base128 = ((size_t)t * Bc + (gb + s)) * 128;
                    out[OFF_SDXU + base128 + tid] = relu_f(dn - bu[s]) + relu_f(bu[s] - dx);
                    out[OFF_SDXD + base128 + tid] = relu_f(dn - ed[s]) + relu_f(ed[s] - dx);
                    g_C[base128 + tid] = bu[s] + ed[s] + bv;
                }
            } else if (uo >= 0 && uo < 32) {
                #pragma unroll
                for (int s = 0; s < 4; s++) {
                    float uu = u_sh[pv * 128 + s * 32 + uo];
                    size_t base32 = tb + (size_t)(gb + s) * 32;
                    out[OFF_U + base32 + uo]     = uu;
                    out[OFF_SUMIN + base32 + uo] = relu_f(umn_c[s] - uu);
                    out[OFF_SUMAX + base32 + uo] = relu_f(uu - umx_c[s]);
                }
            }
        }
        if (uo >= 0 && uo < 32) {
            #pragma unroll
            for (int s = 0; s < 4; s++) { umn_c[s] = umn_n[s]; umx_c[s] = umx_n[s]; }
        }
        __syncthreads();
    }
}

// ---------------- kernel: C2 = Ceven @ WA + Codd  (register-tiled GEMM) ------
// grid 1024: p = blk>>1, half = blk&1. Tile: 64 rows (batch) x 128 cols.
// Thread computes 4x8 register tile; WA + X tile in dynamic smem (96 KB).
#define SM_C2_BYTES ((64*128 + 128*128) * 4)
__global__ void __launch_bounds__(256) k_c2(const float* __restrict__ Cg)
{
    extern __shared__ float smc[];
    float* Xs = smc;            // 64 x 128
    float* Ws = smc + 8192;     // 128 x 128
    int tid = threadIdx.x;
    int p = blockIdx.x >> 1;
    int half = blockIdx.x & 1;

    // load WA (4096 f4) and X tile (2048 f4)
    {
        const float4* wsrc = (const float4*)g_WA;
        float4* wdst = (float4*)Ws;
        #pragma unroll
        for (int i = 0; i < 16; i++) wdst[tid + i * 256] = wsrc[tid + i * 256];
        const float4* xsrc = (const float4*)(Cg + ((size_t)(2 * p) * Bc + half * 64) * 128);
        float4* xdst = (float4*)Xs;
        #pragma unroll
        for (int i = 0; i < 8; i++) xdst[tid + i * 256] = xsrc[tid + i * 256];
    }
    __syncthreads();

    int rg = tid >> 4;          // 16 row groups of 4
    int cg = tid & 15;          // 16 col groups of 8
    float acc[4][8];
    #pragma unroll
    for (int i = 0; i < 4; i++)
        #pragma unroll
        for (int c = 0; c < 8; c++) acc[i][c] = 0.0f;

    const float4* Xf4 = (const float4*)Xs;
    const float4* Wf4 = (const float4*)Ws;
    #pragma unroll 8
    for (int k4 = 0; k4 < 32; k4++) {
        float4 wv[4][2];
        #pragma unroll
        for (int kk = 0; kk < 4; kk++) {
            wv[kk][0] = Wf4[(k4 * 4 + kk) * 32 + cg * 2];
            wv[kk][1] = Wf4[(k4 * 4 + kk) * 32 + cg * 2 + 1];
        }
        #pragma unroll
        for (int i = 0; i < 4; i++) {
            float4 xv = Xf4[(rg * 4 + i) * 32 + k4];
            #pragma unroll
            for (int hc = 0; hc < 2; hc++) {
                acc[i][hc * 4 + 0] = fmaf(xv.x, wv[0][hc].x, acc[i][hc * 4 + 0]);
                acc[i][hc * 4 + 1] = fmaf(xv.x, wv[0][hc].y, acc[i][hc * 4 + 1]);
                acc[i][hc * 4 + 2] = fmaf(xv.x, wv[0][hc].z, acc[i][hc * 4 + 2]);
                acc[i][hc * 4 + 3] = fmaf(xv.x, wv[0][hc].w, acc[i][hc * 4 + 3]);
                acc[i][hc * 4 + 0] = fmaf(xv.y, wv[1][hc].x, acc[i][hc * 4 + 0]);
                acc[i][hc * 4 + 1] = fmaf(xv.y, wv[1][hc].y, acc[i][hc * 4 + 1]);
                acc[i][hc * 4 + 2] = fmaf(xv.y, wv[1][hc].z, acc[i][hc * 4 + 2]);
                acc[i][hc * 4 + 3] = fmaf(xv.y, wv[1][hc].w, acc[i][hc * 4 + 3]);
                acc[i][hc * 4 + 0] = fmaf(xv.z, wv[2][hc].x, acc[i][hc * 4 + 0]);
                acc[i][hc * 4 + 1] = fmaf(xv.z, wv[2][hc].y, acc[i][hc * 4 + 1]);
                acc[i][hc * 4 + 2] = fmaf(xv.z, wv[2][hc].z, acc[i][hc * 4 + 2]);
                acc[i][hc * 4 + 3] = fmaf(xv.z, wv[2][hc].w, acc[i][hc * 4 + 3]);
                acc[i][hc * 4 + 0] = fmaf(xv.w, wv[3][hc].x, acc[i][hc * 4 + 0]);
                acc[i][hc * 4 + 1] = fmaf(xv.w, wv[3][hc].y, acc[i][hc * 4 + 1]);
                acc[i][hc * 4 + 2] = fmaf(xv.w, wv[3][hc].z, acc[i][hc * 4 + 2]);
                acc[i][hc * 4 + 3] = fmaf(xv.w, wv[3][hc].w, acc[i][hc * 4 + 3]);
            }
        }
    }

    // epilogue: add Codd, write C2
    const float* codd = Cg + ((size_t)(2 * p + 1) * Bc + half * 64) * 128;
    float* o = g_C2 + ((size_t)p * Bc + half * 64) * 128;
    #pragma unroll
    for (int i = 0; i < 4; i++) {
        int row = rg * 4 + i;
        const float4* co = (const float4*)(codd + row * 128) + cg * 2;
        float4* od = (float4*)(o + row * 128) + cg * 2;
        float4 c0 = co[0], c1 = co[1];
        od[0] = make_float4(acc[i][0] + c0.x, acc[i][1] + c0.y,
                            acc[i][2] + c0.z, acc[i][3] + c0.w);
        od[1] = make_float4(acc[i][4] + c1.x, acc[i][5] + c1.y,
                            acc[i][6] + c1.z, acc[i][7] + c1.w);
    }
}

// ---------------- kernel 5: sequential rollout, 2 steps per barrier ----------
__global__ void __launch_bounds__(256) k_seq(
    const float* __restrict__ XMIN, const float* __restrict__ XMAX,
    const float* __restrict__ Cg, float* __restrict__ out)
{
    __shared__ float xbuf[2][128];
    int tid = threadIdx.x;
    int b = blockIdx.x;
    int j = tid >> 1, h = tid & 1;

    float wa[64], wa2[64];
    #pragma unroll
    for (int kk = 0; kk < 64; kk++) {
        wa[kk]  = g_WA [(h * 64 + kk) * 128 + j];
        wa2[kk] = g_WA2[(h * 64 + kk) * 128 + j];
    }

    float xprev = g_x0[b * 128 + j];
    if (h == 0) xbuf[0][j] = xprev;

    float cA[2], mnr[2], mxr[2];
    #pragma unroll
    for (int pp = 0; pp < 2; pp++) {
        int ts = 2 * pp + h;
        size_t ib = ((size_t)ts * Bc + b) * 128 + j;
        mnr[pp] = XMIN[ib];
        mxr[pp] = XMAX[ib];
        cA[pp] = h ? g_C2[((size_t)pp * Bc + b) * 128 + j] : Cg[ib];
    }
    __syncthreads();

    for (int p = 0; p < NSTEPSc / 2; p++) {
        int cur = p & 1;
        const float4* x4 = ((const float4*)xbuf[cur]) + h * 16;
        float p1a = 0.f, p1b = 0.f, p2a = 0.f, p2b = 0.f;
        #pragma unroll
        for (int kk = 0; kk < 16; kk++) {
            float4 xv = x4[kk];
            p1a = fmaf(xv.x, wa[kk * 4 + 0], p1a);
            p1b = fmaf(xv.y, wa[kk * 4 + 1], p1b);
            p1a = fmaf(xv.z, wa[kk * 4 + 2], p1a);
            p1b = fmaf(xv.w, wa[kk * 4 + 3], p1b);
            p2a = fmaf(xv.x, wa2[kk * 4 + 0], p2a);
            p2b = fmaf(xv.y, wa2[kk * 4 + 1], p2b);
            p2a = fmaf(xv.z, wa2[kk * 4 + 2], p2a);
            p2b = fmaf(xv.w, wa2[kk * 4 + 3], p2b);
        }
        float y1p = p1a + p1b, y2p = p2a + p2b;
        float y1o = __shfl_xor_sync(0xffffffffu, y1p, 1);
        float y2o = __shfl_xor_sync(0xffffffffu, y2p, 1);
        float cmine = cA[cur];
        float coth  = __shfl_xor_sync(0xffffffffu, cmine, 1);
        float ct = h ? coth : cmine;
        float c2 = h ? cmine : coth;
        float y1 = y1p + y1o + ct;
        float y2 = y2p + y2o + c2;

        int ts = 2 * p + h;
        size_t bi = ((size_t)ts * Bc + b) * 128 + j;
        float yv = h ? y2 : y1;
        out[OFF_X + bi]     = yv;
        out[OFF_SXMIN + bi] = relu_f(mnr[cur] - yv);
        out[OFF_SXMAX + bi] = relu_f(yv - mxr[cur]);
        out[OFF_SDXX + bi]  = h ? (y2 - y1) : (y1 - xprev);
        xprev = y2;
        if (h == 0) xbuf[1 - cur][j] = y2;

        if (p + 2 < NSTEPSc / 2) {
            int tn = 2 * (p + 2) + h;
            size_t ib = ((size_t)tn * Bc + b) * 128 + j;
            mnr[cur] = XMIN[ib];
            mxr[cur] = XMAX[ib];
            cA[cur] = h ? g_C2[((size_t)(p + 2) * Bc + b) * 128 + j] : Cg[ib];
        }
        __syncthreads();
    }
}

// ---------------- kernel 6: Y = X @ W_C (register-tiled GEMM) ----------------
// grid 2048: 64-row tiles. Thread computes 4x4 tile; X + W_C in smem (64 KB).
#define SM_POST_BYTES ((64*128 + 128*64) * 4)
__global__ void __launch_bounds__(256) k_post(float* __restrict__ out)
{
    extern __shared__ float smp[];
    float* Xs = smp;            // 64 x 128
    float* Ws = smp + 8192;     // 128 x 64
    int tid = threadIdx.x;
    size_t row0 = (size_t)blockIdx.x * 64;

    {
        const float4* wsrc = (const float4*)g_WC;
        float4* wdst = (float4*)Ws;
        #pragma unroll
        for (int i = 0; i < 8; i++) wdst[tid + i * 256] = wsrc[tid + i * 256];
        const float4* xsrc = (const float4*)(out + OFF_X + row0 * 128);
        float4* xdst = (float4*)Xs;
        #pragma unroll
        for (int i = 0; i < 8; i++) xdst[tid + i * 256] = xsrc[tid + i * 256];
    }
    __syncthreads();

    int rg = tid >> 4;          // 16 row groups of 4
    int cg = tid & 15;          // 16 col groups of 4
    float acc[4][4];
    #pragma unroll
    for (int i = 0; i < 4; i++)
        #pragma unroll
        for (int c = 0; c < 4; c++) acc[i][c] = 0.0f;

    const float4* Xf4 = (const float4*)Xs;
    const float4* Wf4 = (const float4*)Ws;
    #pragma unroll 8
    for (int k4 = 0; k4 < 32; k4++) {
        float4 wv[4];
        #pragma unroll
        for (int kk = 0; kk < 4; kk++)
            wv[kk] = Wf4[(k4 * 4 + kk) * 16 + cg];
        #pragma unroll
        for (int i = 0; i < 4; i++) {
            float4 xv = Xf4[(rg * 4 + i) * 32 + k4];
            acc[i][0] = fmaf(xv.x, wv[0].x, acc[i][0]);
            acc[i][1] = fmaf(xv.x, wv[0].y, acc[i][1]);
            acc[i][2] = fmaf(xv.x, wv[0].z, acc[i][2]);
            acc[i][3] = fmaf(xv.x, wv[0].w, acc[i][3]);
            acc[i][0] = fmaf(xv.y, wv[1].x, acc[i][0]);
            acc[i][1] = fmaf(xv.y, wv[1].y, acc[i][1]);
            acc[i][2] = fmaf(xv.y, wv[1].z, acc[i][2]);
            acc[i][3] = fmaf(xv.y, wv[1].w, acc[i][3]);
            acc[i][0] = fmaf(xv.z, wv[2].x, acc[i][0]);
            acc[i][1] = fmaf(xv.z, wv[2].y, acc[i][1]);
            acc[i][2] = fmaf(xv.z, wv[2].z, acc[i][2]);
            acc[i][3] = fmaf(xv.z, wv[2].w, acc[i][3]);
            acc[i][0] = fmaf(xv.w, wv[3].x, acc[i][0]);
            acc[i][1] = fmaf(xv.w, wv[3].y, acc[i][1]);
            acc[i][2] = fmaf(xv.w, wv[3].z, acc[i][2]);
            acc[i][3] = fmaf(xv.w, wv[3].w, acc[i][3]);
        }
    }

    #pragma unroll
    for (int i = 0; i < 4; i++) {
        float4* od = (float4*)(out + OFF_Y + (row0 + rg * 4 + i) * 64) + cg;
        od[0] = make_float4(acc[i][0], acc[i][1], acc[i][2], acc[i][3]);
    }
}

// ---------------- launch ------------------------------------------------------
extern "C" void kernel_launch(void* const* d_in, const int* in_sizes, int n_in,
                              void* d_out, int out_size)
{
    const float* Ym   = (const float*)d_in[0];
    const float* M    = (const float*)d_in[1];
    const float* DTin = (const float*)d_in[2];
    const float* Din  = (const float*)d_in[3];
    const float* XMIN = (const float*)d_in[4];
    const float* XMAX = (const float*)d_in[5];
    const float* UMIN = (const float*)d_in[6];
    const float* UMAX = (const float*)d_in[7];
    const float* x0c  = (const float*)d_in[8];
    const float* UA   = (const float*)d_in[9];
    const float* sigA = (const float*)d_in[10];
    const float* VA   = (const float*)d_in[11];
    const float* UC   = (const float*)d_in[12];
    const float* sigC = (const float*)d_in[13];
    const float* VC   = (const float*)d_in[14];
    const float* wE   = (const float*)d_in[15];
    const float* sE   = (const float*)d_in[16];
    const float* wB   = (const float*)d_in[17];
    const float* Whf  = (const float*)d_in[18];
    const float* Wih  = (const float*)d_in[19];
    const float* Whh  = (const float*)d_in[20];
    const float* dxmn = (const float*)d_in[21];
    const float* dxmx = (const float*)d_in[22];
    float* out = (float*)d_out;

    static const size_t smem_pre = SM_PRE_FLOATS * sizeof(float);
    cudaFuncSetAttribute(k_pre, cudaFuncAttributeMaxDynamicSharedMemorySize,
                         (int)smem_pre);
    cudaFuncSetAttribute(k_c2, cudaFuncAttributeMaxDynamicSharedMemorySize,
                         SM_C2_BYTES);
    cudaFuncSetAttribute(k_post, cudaFuncAttributeMaxDynamicSharedMemorySize,
                         SM_POST_BYTES);

    float* Cg = nullptr;
    cudaGetSymbolAddress((void**)&Cg, g_C);

    k_zero<<<1, 32>>>();
    k_setup<<<128, 128>>>(UA, sigA, VA, UC, sigC, VC);
    k_setup2<<<1, 128>>>(x0c, wE, sE, wB, out);
    k_pre<<<NSTEPSc, 512, smem_pre>>>(M, DTin, Din, UMIN, UMAX, Whf, dxmn, dxmx, out);
    k_wa2<<<128, 128>>>();
    k_rnn<<<Bc, 512>>>(Ym, Wih, Whh);
    k_c2<<<NSTEPSc, 256, SM_C2_BYTES>>>(Cg);
    k_seq<<<Bc, 256>>>(XMIN, XMAX, Cg, out);
    k_post<<<(NSTEPSc * Bc) / 64, 256, SM_POST_BYTES>>>(out);
}